// round 9
// baseline (speedup 1.0000x reference)
#include <cuda_runtime.h>
#include <cstdint>

// ---------------------------------------------------------------------------
// ParticleExplorer — fused time-parallel kernel, L=16 chunks, 2 warps/particle,
// in-place smem reuse for X staging (52.5 KB/block -> 4 blocks/SM).
// Per step: E <- E * Rz(pa) * Ry(na);  x <- x + sp * E.col0
// N = 1024 = 64 chunks x 16 steps. Block = 8 warps = 4 particles.
//   stage : coalesced float4 loads -> smem (pitch-34), aux outputs folded in
//   pass 1: 16-step chunk transform (P,d) from identity
//   scan  : intra-warp shfl scan + cross-half 12-float smem handoff
//   glue  : compose with (E0,x0), Gram-Schmidt renorm
//   pass 2: replay 16 steps; (x,y,z) overwrite the just-consumed (sp,pa,na)
//           smem slots; coalesced float4 flush gathers from [step][chunk].
// Output: ts[N] | X[B][N][3] | states[B][N]=0 | speeds | pa | na
// ---------------------------------------------------------------------------

#define LCH 16
#define NWARP 8
#define THREADS (NWARP * 32)

#define SIN_PITCH 34
#define SIN_W (LCH * SIN_PITCH)                       // 544 floats per array
#define GLUE_OFF (NWARP * (3 * SIN_W))                // 13056
#define SMEM_FLOATS (GLUE_OFF + 4 * 16)               // + glue (4 particles x 16)

__device__ __forceinline__ void frame_step(float pa, float na,
    float& a0, float& a1, float& a2,
    float& b0, float& b1, float& b2,
    float& c0, float& c1, float& c2)
{
    float s1, cc1, s2, cc2;
    __sincosf(pa, &s1, &cc1);
    __sincosf(na, &s2, &cc2);
    float p00 = cc1 * cc2, p10 = s1 * cc2;
    float p02 = cc1 * s2,  p12 = s1 * s2;

    float na0 = fmaf(p00, a0, fmaf(p10, b0, -s2 * c0));
    float na1 = fmaf(p00, a1, fmaf(p10, b1, -s2 * c1));
    float na2 = fmaf(p00, a2, fmaf(p10, b2, -s2 * c2));
    float nb0 = fmaf(cc1, b0, -s1 * a0);
    float nb1 = fmaf(cc1, b1, -s1 * a1);
    float nb2 = fmaf(cc1, b2, -s1 * a2);
    float nc0 = fmaf(p02, a0, fmaf(p12, b0, cc2 * c0));
    float nc1 = fmaf(p02, a1, fmaf(p12, b1, cc2 * c1));
    float nc2 = fmaf(p02, a2, fmaf(p12, b2, cc2 * c2));
    a0 = na0; a1 = na1; a2 = na2;
    b0 = nb0; b1 = nb1; b2 = nb2;
    c0 = nc0; c1 = nc1; c2 = nc2;
}

// Affine compose: r earlier, q later (coeffs in r's start basis).
__device__ __forceinline__ void compose(const float* __restrict__ r,
                                        const float* __restrict__ q,
                                        float* __restrict__ o)
{
    #pragma unroll
    for (int col = 0; col < 3; col++) {
        float q0 = q[col*3+0], q1 = q[col*3+1], q2 = q[col*3+2];
        o[col*3+0] = fmaf(q0, r[0], fmaf(q1, r[3], q2 * r[6]));
        o[col*3+1] = fmaf(q0, r[1], fmaf(q1, r[4], q2 * r[7]));
        o[col*3+2] = fmaf(q0, r[2], fmaf(q1, r[5], q2 * r[8]));
    }
    float d0 = q[9], d1 = q[10], d2 = q[11];
    o[9]  = fmaf(d0, r[0], fmaf(d1, r[3], fmaf(d2, r[6], r[9])));
    o[10] = fmaf(d0, r[1], fmaf(d1, r[4], fmaf(d2, r[7], r[10])));
    o[11] = fmaf(d0, r[2], fmaf(d1, r[5], fmaf(d2, r[8], r[11])));
}

__global__ void __launch_bounds__(THREADS)
fused_kernel(const float* __restrict__ x0, const float* __restrict__ e0i,
             const float* __restrict__ e1i, const float* __restrict__ e2i,
             const float* __restrict__ spd, const float* __restrict__ pan,
             const float* __restrict__ nanp,
             float* __restrict__ ts, float* __restrict__ X,
             float* __restrict__ states, float* __restrict__ spo,
             float* __restrict__ pao, float* __restrict__ nao,
             const int* __restrict__ dtp, int B, int N)
{
    extern __shared__ float sm[];

    const int tid  = threadIdx.x;
    const int lane = tid & 31;
    const int w    = tid >> 5;
    const int h    = w & 1;                 // half (0: steps 0..511, 1: 512..1023)
    const int ps   = w >> 1;                // particle slot in block
    const int p    = blockIdx.x * 4 + ps;
    const int gtid = blockIdx.x * THREADS + tid;

    if (gtid < N) {
        float dtf = 1.0f;
        if (dtp) {
            int vdt = dtp[0];
            if (vdt >= 1 && vdt <= 1000000) dtf = (float)vdt;
            else { float f = __int_as_float(vdt); if (f > 0.f && f < 1.0e6f) dtf = f; }
        }
        ts[gtid] = (float)gtid * dtf;
    }
    // No early return: __syncthreads below needs all threads (grid == B/4 exact).

    float* s_sp = sm + w * (3 * SIN_W);
    float* s_pa = s_sp + SIN_W;
    float* s_na = s_sp + 2 * SIN_W;
    float* glue = sm + GLUE_OFF + ps * 16;

    const size_t pb = (size_t)p * N + (size_t)h * 512;
    const float4* g_sp = (const float4*)(spd  + pb);
    const float4* g_pa = (const float4*)(pan  + pb);
    const float4* g_na = (const float4*)(nanp + pb);
    float4* o_sp = (float4*)(spo    + pb);
    float4* o_pa = (float4*)(pao    + pb);
    float4* o_na = (float4*)(nao    + pb);
    float4* o_st = (float4*)(states + pb);
    const float4 zero4 = make_float4(0.f, 0.f, 0.f, 0.f);

    // ---- Stage: coalesced loads -> smem [step i][chunk], pitch 34.
    #pragma unroll
    for (int j = 0; j < 4; j++) {
        int f = j * 32 + lane;
        float4 vs = g_sp[f], vp = g_pa[f], vn = g_na[f];
        o_sp[f] = vs; o_pa[f] = vp; o_na[f] = vn; o_st[f] = zero4;
        int cih = j * 8 + (lane >> 2);
        int i0  = (lane & 3) << 2;
        s_sp[(i0+0)*SIN_PITCH + cih] = vs.x; s_sp[(i0+1)*SIN_PITCH + cih] = vs.y;
        s_sp[(i0+2)*SIN_PITCH + cih] = vs.z; s_sp[(i0+3)*SIN_PITCH + cih] = vs.w;
        s_pa[(i0+0)*SIN_PITCH + cih] = vp.x; s_pa[(i0+1)*SIN_PITCH + cih] = vp.y;
        s_pa[(i0+2)*SIN_PITCH + cih] = vp.z; s_pa[(i0+3)*SIN_PITCH + cih] = vp.w;
        s_na[(i0+0)*SIN_PITCH + cih] = vn.x; s_na[(i0+1)*SIN_PITCH + cih] = vn.y;
        s_na[(i0+2)*SIN_PITCH + cih] = vn.z; s_na[(i0+3)*SIN_PITCH + cih] = vn.w;
    }
    __syncwarp();

    // ---- Pass 1: 16-step chunk transform from identity -------------------------
    float a0=1.f,a1=0.f,a2=0.f, b0=0.f,b1=1.f,b2=0.f, c0=0.f,c1=0.f,c2=1.f;
    float d0=0.f,d1=0.f,d2=0.f;
    #pragma unroll 4
    for (int i = 0; i < LCH; i++) {
        float pa = s_pa[i*SIN_PITCH + lane];
        float na = s_na[i*SIN_PITCH + lane];
        float sp = s_sp[i*SIN_PITCH + lane];
        frame_step(pa, na, a0,a1,a2,b0,b1,b2,c0,c1,c2);
        d0 = fmaf(sp,a0,d0); d1 = fmaf(sp,a1,d1); d2 = fmaf(sp,a2,d2);
    }

    float v[12] = {a0,a1,a2, b0,b1,b2, c0,c1,c2, d0,d1,d2};

    // ---- Intra-warp inclusive scan (affine composition) -----------------------
    #pragma unroll
    for (int off = 1; off <= 16; off <<= 1) {
        float o[12];
        #pragma unroll
        for (int i = 0; i < 12; i++)
            o[i] = __shfl_up_sync(0xffffffffu, v[i], off);
        if (lane >= off) {
            float t[12];
            compose(o, v, t);
            #pragma unroll
            for (int i = 0; i < 12; i++) v[i] = t[i];
        }
    }

    // Half-0 publishes its total (lane 31 inclusive) for half-1.
    if (h == 0 && lane == 31) {
        #pragma unroll
        for (int i = 0; i < 12; i++) glue[i] = v[i];
    }
    __syncthreads();

    // Exclusive prefix within warp.
    float e[12];
    #pragma unroll
    for (int i = 0; i < 12; i++)
        e[i] = __shfl_up_sync(0xffffffffu, v[i], 1);
    if (lane == 0) {
        e[0]=1.f; e[1]=0.f; e[2]=0.f;
        e[3]=0.f; e[4]=1.f; e[5]=0.f;
        e[6]=0.f; e[7]=0.f; e[8]=1.f;
        e[9]=0.f; e[10]=0.f; e[11]=0.f;
    }
    // Half-1: prepend half-0's total.
    if (h == 1) {
        float T0[12];
        #pragma unroll
        for (int i = 0; i < 12; i++) T0[i] = glue[i];
        float t[12];
        compose(T0, e, t);
        #pragma unroll
        for (int i = 0; i < 12; i++) e[i] = t[i];
    }

    // ---- Glue with particle initial frame/pos ----------------------------------
    float A0=e0i[p*3+0], A1=e0i[p*3+1], A2=e0i[p*3+2];
    float B0=e1i[p*3+0], B1=e1i[p*3+1], B2=e1i[p*3+2];
    float C0=e2i[p*3+0], C1=e2i[p*3+1], C2=e2i[p*3+2];
    float x =x0 [p*3+0], y =x0 [p*3+1], z =x0 [p*3+2];

    a0 = fmaf(e[0],A0, fmaf(e[1],B0, e[2]*C0));
    a1 = fmaf(e[0],A1, fmaf(e[1],B1, e[2]*C1));
    a2 = fmaf(e[0],A2, fmaf(e[1],B2, e[2]*C2));
    b0 = fmaf(e[3],A0, fmaf(e[4],B0, e[5]*C0));
    b1 = fmaf(e[3],A1, fmaf(e[4],B1, e[5]*C1));
    b2 = fmaf(e[3],A2, fmaf(e[4],B2, e[5]*C2));
    c0 = fmaf(e[6],A0, fmaf(e[7],B0, e[8]*C0));
    c1 = fmaf(e[6],A1, fmaf(e[7],B1, e[8]*C1));
    c2 = fmaf(e[6],A2, fmaf(e[7],B2, e[8]*C2));
    x  = fmaf(e[9],A0, fmaf(e[10],B0, fmaf(e[11],C0, x)));
    y  = fmaf(e[9],A1, fmaf(e[10],B1, fmaf(e[11],C1, y)));
    z  = fmaf(e[9],A2, fmaf(e[10],B2, fmaf(e[11],C2, z)));

    // Gram-Schmidt renorm (kills composition drift).
    {
        float inv = rsqrtf(fmaf(a0,a0, fmaf(a1,a1, a2*a2)));
        a0*=inv; a1*=inv; a2*=inv;
        float dd = fmaf(b0,a0, fmaf(b1,a1, b2*a2));
        b0 = fmaf(-dd,a0,b0); b1 = fmaf(-dd,a1,b1); b2 = fmaf(-dd,a2,b2);
        inv = rsqrtf(fmaf(b0,b0, fmaf(b1,b1, b2*b2)));
        b0*=inv; b1*=inv; b2*=inv;
        c0 = a1*b2 - a2*b1;
        c1 = a2*b0 - a0*b2;
        c2 = a0*b1 - a1*b0;
    }

    // ---- Pass 2: replay 16 steps; (x,y,z) overwrite (sp,pa,na) in place --------
    // Slot [i*34+lane] is read only by this lane in pass 2, so read-then-write
    // within the iteration is race-free.
    #pragma unroll 4
    for (int i = 0; i < LCH; i++) {
        float pa = s_pa[i*SIN_PITCH + lane];
        float na = s_na[i*SIN_PITCH + lane];
        float sp = s_sp[i*SIN_PITCH + lane];
        frame_step(pa, na, a0,a1,a2,b0,b1,b2,c0,c1,c2);
        x = fmaf(sp,a0,x); y = fmaf(sp,a1,y); z = fmaf(sp,a2,z);
        s_sp[i*SIN_PITCH + lane] = x;
        s_pa[i*SIN_PITCH + lane] = y;
        s_na[i*SIN_PITCH + lane] = z;
    }
    __syncwarp();

    // ---- Flush X: warp's half = 1536 consecutive floats = 384 float4. ----------
    // Element e (0..1535) = own*48 + i*3 + comp, stored in array 'comp' at
    // [i*34 + own]. Gather 4 elements per lane, store one float4 (coalesced).
    float4* gX = (float4*)(X + (size_t)p * 3 * N + (size_t)h * 1536);
    #pragma unroll
    for (int j = 0; j < 12; j++) {
        int L4 = j * 32 + lane;
        float r[4];
        #pragma unroll
        for (int k = 0; k < 4; k++) {
            int ek   = 4 * L4 + k;
            int own  = ek / 48;
            int rem  = ek - own * 48;
            int i    = rem / 3;
            int comp = rem - i * 3;
            const float* arr = (comp == 0) ? s_sp : (comp == 1) ? s_pa : s_na;
            r[k] = arr[i * SIN_PITCH + own];
        }
        gX[L4] = make_float4(r[0], r[1], r[2], r[3]);
    }
}

// ---------------------------------------------------------------------------
// Fallback (proven round-2 path) for unexpected shapes.
// ---------------------------------------------------------------------------
#define PPB 32
#define TT  32
#define SPITCH 33

__global__ void __launch_bounds__(PPB)
explorer_kernel(const float* __restrict__ x0, const float* __restrict__ e0i,
                const float* __restrict__ e1i, const float* __restrict__ e2i,
                const float* __restrict__ spd, const float* __restrict__ pan,
                const float* __restrict__ nan_, float* __restrict__ X,
                int B, int N)
{
    __shared__ float s_sp[TT][SPITCH];
    __shared__ float s_pa[TT][SPITCH];
    __shared__ float s_na[TT][SPITCH];
    __shared__ float s_X[3 * TT][SPITCH];

    const int lane  = threadIdx.x;
    const int pbase = blockIdx.x * PPB;
    const int p     = pbase + lane;
    const bool act  = (p < B);

    float a0=1.f,a1=0.f,a2=0.f, b0=0.f,b1=1.f,b2=0.f, c0=0.f,c1=0.f,c2=1.f;
    float x=0.f, y=0.f, z=0.f;
    if (act) {
        a0=e0i[p*3+0]; a1=e0i[p*3+1]; a2=e0i[p*3+2];
        b0=e1i[p*3+0]; b1=e1i[p*3+1]; b2=e1i[p*3+2];
        c0=e2i[p*3+0]; c1=e2i[p*3+1]; c2=e2i[p*3+2];
        x =x0 [p*3+0]; y =x0 [p*3+1]; z =x0 [p*3+2];
    }

    for (int t0 = 0; t0 < N; t0 += TT) {
        #pragma unroll
        for (int k = 0; k < PPB; k++) {
            int gp = pbase + k;
            float vs=0.f, vp=0.f, vn=0.f;
            if (gp < B && t0 + lane < N) {
                size_t gidx = (size_t)gp * N + (size_t)t0 + lane;
                vs = spd[gidx]; vp = pan[gidx]; vn = nan_[gidx];
            }
            s_sp[lane][k]=vs; s_pa[lane][k]=vp; s_na[lane][k]=vn;
        }
        __syncthreads();

        if (act) {
            int nt = (N - t0 < TT) ? (N - t0) : TT;
            for (int tt = 0; tt < nt; tt++) {
                frame_step(s_pa[tt][lane], s_na[tt][lane],
                           a0,a1,a2,b0,b1,b2,c0,c1,c2);
                float s = s_sp[tt][lane];
                x = fmaf(s,a0,x); y = fmaf(s,a1,y); z = fmaf(s,a2,z);
                s_X[3*tt+0][lane]=x; s_X[3*tt+1][lane]=y; s_X[3*tt+2][lane]=z;
            }
            float inv = rsqrtf(fmaf(a0,a0, fmaf(a1,a1, a2*a2)));
            a0*=inv; a1*=inv; a2*=inv;
            float d = fmaf(b0,a0, fmaf(b1,a1, b2*a2));
            b0=fmaf(-d,a0,b0); b1=fmaf(-d,a1,b1); b2=fmaf(-d,a2,b2);
            inv = rsqrtf(fmaf(b0,b0, fmaf(b1,b1, b2*b2)));
            b0*=inv; b1*=inv; b2*=inv;
            c0=a1*b2-a2*b1; c1=a2*b0-a0*b2; c2=a0*b1-a1*b0;
        }
        __syncthreads();

        #pragma unroll
        for (int k = 0; k < PPB; k++) {
            int gp = pbase + k;
            if (gp < B) {
                size_t bidx = (size_t)gp*3*N + (size_t)t0*3;
                #pragma unroll
                for (int chn = 0; chn < 3; chn++)
                    if (t0*3 + chn*32 + lane < 3*N)
                        X[bidx + chn*32 + lane] = s_X[chn*32 + lane][k];
            }
        }
    }
}

__global__ void ts_kernel(float* __restrict__ ts, int N, const int* __restrict__ dtp)
{
    int i = blockIdx.x * blockDim.x + threadIdx.x;
    if (i >= N) return;
    float dtf = 1.0f;
    if (dtp != nullptr) {
        int v = dtp[0];
        if (v >= 1 && v <= 1000000) dtf = (float)v;
        else { float f = __int_as_float(v); if (f > 0.0f && f < 1.0e6f) dtf = f; }
    }
    ts[i] = (float)i * dtf;
}

// ---------------------------------------------------------------------------
extern "C" void kernel_launch(void* const* d_in, const int* in_sizes, int n_in,
                              void* d_out, int out_size)
{
    const float* x0   = (const float*)d_in[0];
    const float* e0   = (const float*)d_in[1];
    const float* e1   = (const float*)d_in[2];
    const float* e2   = (const float*)d_in[3];
    const float* spd  = (const float*)d_in[4];
    const float* pan  = (const float*)d_in[5];
    const float* nan_ = (const float*)d_in[6];

    const int B = in_sizes[0] / 3;
    const int N = (int)((long long)in_sizes[4] / B);

    float* out    = (float*)d_out;
    float* ts     = out;
    float* X      = out + N;
    float* states = X + (size_t)3 * B * N;
    float* sp_o   = states + (size_t)B * N;
    float* pa_o   = sp_o   + (size_t)B * N;
    float* na_o   = pa_o   + (size_t)B * N;

    const int* dtp = (n_in > 8) ? (const int*)d_in[8] : nullptr;

    const size_t smem_bytes = (size_t)SMEM_FLOATS * sizeof(float);  // ~52.5 KB
    const bool fast = (N == 1024) && (B % 4 == 0);

    if (fast) {
        cudaFuncSetAttribute(fused_kernel,
                             cudaFuncAttributeMaxDynamicSharedMemorySize,
                             (int)smem_bytes);
        fused_kernel<<<B / 4, THREADS, smem_bytes>>>(
            x0, e0, e1, e2, spd, pan, nan_,
            ts, X, states, sp_o, pa_o, na_o, dtp, B, N);
    } else {
        const size_t bn_bytes = (size_t)B * N * sizeof(float);
        explorer_kernel<<<(B + PPB - 1) / PPB, PPB>>>(x0, e0, e1, e2,
                                                      spd, pan, nan_, X, B, N);
        ts_kernel<<<(N + 255) / 256, 256>>>(ts, N, dtp);
        cudaMemsetAsync(states, 0, bn_bytes, 0);
        cudaMemcpyAsync(sp_o, d_in[4], bn_bytes, cudaMemcpyDeviceToDevice, 0);
        cudaMemcpyAsync(pa_o, d_in[5], bn_bytes, cudaMemcpyDeviceToDevice, 0);
        cudaMemcpyAsync(na_o, d_in[6], bn_bytes, cudaMemcpyDeviceToDevice, 0);
    }

    (void)out_size; (void)n_in;
}

// round 10
// speedup vs baseline: 1.1091x; 1.1091x over previous
#include <cuda_runtime.h>
#include <cstdint>

// ---------------------------------------------------------------------------
// ParticleExplorer — fused time-parallel kernel, L=16 chunks, 2 warps/particle,
// in-place smem reuse; pass 2 is a 9-FMA matvec (displacement trick).
// Per step: E <- E * Rz(pa) * Ry(na);  x <- x + sp * E.col0
// N = 1024 = 64 chunks x 16 steps. Block = 8 warps = 4 particles.
//   stage : coalesced float4 loads -> smem (pitch-34), aux outputs folded in
//   pass 1: 16-step chunk transform; running local displacement d_i is stored
//           over the just-consumed (sp,pa,na) slots (own-column, race-free)
//   scan  : intra-warp shfl scan + cross-half 12-float smem handoff
//   glue  : compose with (E0,x0), Gram-Schmidt renorm
//   pass 2: x_i = x_start + d_i . E_start  (9 FMA/step, no sincos), in place
//   flush : gather [step][chunk] -> coalesced float4 stores
// Output: ts[N] | X[B][N][3] | states[B][N]=0 | speeds | pa | na
// ---------------------------------------------------------------------------

#define LCH 16
#define NWARP 8
#define THREADS (NWARP * 32)

#define SIN_PITCH 34
#define SIN_W (LCH * SIN_PITCH)                       // 544 floats per array
#define GLUE_OFF (NWARP * (3 * SIN_W))                // 13056
#define SMEM_FLOATS (GLUE_OFF + 4 * 16)               // + glue (4 particles x 16)

__device__ __forceinline__ void frame_step(float pa, float na,
    float& a0, float& a1, float& a2,
    float& b0, float& b1, float& b2,
    float& c0, float& c1, float& c2)
{
    float s1, cc1, s2, cc2;
    __sincosf(pa, &s1, &cc1);
    __sincosf(na, &s2, &cc2);
    float p00 = cc1 * cc2, p10 = s1 * cc2;
    float p02 = cc1 * s2,  p12 = s1 * s2;

    float na0 = fmaf(p00, a0, fmaf(p10, b0, -s2 * c0));
    float na1 = fmaf(p00, a1, fmaf(p10, b1, -s2 * c1));
    float na2 = fmaf(p00, a2, fmaf(p10, b2, -s2 * c2));
    float nb0 = fmaf(cc1, b0, -s1 * a0);
    float nb1 = fmaf(cc1, b1, -s1 * a1);
    float nb2 = fmaf(cc1, b2, -s1 * a2);
    float nc0 = fmaf(p02, a0, fmaf(p12, b0, cc2 * c0));
    float nc1 = fmaf(p02, a1, fmaf(p12, b1, cc2 * c1));
    float nc2 = fmaf(p02, a2, fmaf(p12, b2, cc2 * c2));
    a0 = na0; a1 = na1; a2 = na2;
    b0 = nb0; b1 = nb1; b2 = nb2;
    c0 = nc0; c1 = nc1; c2 = nc2;
}

// Affine compose: r earlier, q later (coeffs in r's start basis).
__device__ __forceinline__ void compose(const float* __restrict__ r,
                                        const float* __restrict__ q,
                                        float* __restrict__ o)
{
    #pragma unroll
    for (int col = 0; col < 3; col++) {
        float q0 = q[col*3+0], q1 = q[col*3+1], q2 = q[col*3+2];
        o[col*3+0] = fmaf(q0, r[0], fmaf(q1, r[3], q2 * r[6]));
        o[col*3+1] = fmaf(q0, r[1], fmaf(q1, r[4], q2 * r[7]));
        o[col*3+2] = fmaf(q0, r[2], fmaf(q1, r[5], q2 * r[8]));
    }
    float d0 = q[9], d1 = q[10], d2 = q[11];
    o[9]  = fmaf(d0, r[0], fmaf(d1, r[3], fmaf(d2, r[6], r[9])));
    o[10] = fmaf(d0, r[1], fmaf(d1, r[4], fmaf(d2, r[7], r[10])));
    o[11] = fmaf(d0, r[2], fmaf(d1, r[5], fmaf(d2, r[8], r[11])));
}

__global__ void __launch_bounds__(THREADS)
fused_kernel(const float* __restrict__ x0, const float* __restrict__ e0i,
             const float* __restrict__ e1i, const float* __restrict__ e2i,
             const float* __restrict__ spd, const float* __restrict__ pan,
             const float* __restrict__ nanp,
             float* __restrict__ ts, float* __restrict__ X,
             float* __restrict__ states, float* __restrict__ spo,
             float* __restrict__ pao, float* __restrict__ nao,
             const int* __restrict__ dtp, int B, int N)
{
    extern __shared__ float sm[];

    const int tid  = threadIdx.x;
    const int lane = tid & 31;
    const int w    = tid >> 5;
    const int h    = w & 1;                 // half (0: steps 0..511, 1: 512..1023)
    const int ps   = w >> 1;                // particle slot in block
    const int p    = blockIdx.x * 4 + ps;
    const int gtid = blockIdx.x * THREADS + tid;

    if (gtid < N) {
        float dtf = 1.0f;
        if (dtp) {
            int vdt = dtp[0];
            if (vdt >= 1 && vdt <= 1000000) dtf = (float)vdt;
            else { float f = __int_as_float(vdt); if (f > 0.f && f < 1.0e6f) dtf = f; }
        }
        ts[gtid] = (float)gtid * dtf;
    }
    // No early return: __syncthreads below needs all threads (grid == B/4 exact).

    float* s_sp = sm + w * (3 * SIN_W);
    float* s_pa = s_sp + SIN_W;
    float* s_na = s_sp + 2 * SIN_W;
    float* glue = sm + GLUE_OFF + ps * 16;

    const size_t pb = (size_t)p * N + (size_t)h * 512;
    const float4* g_sp = (const float4*)(spd  + pb);
    const float4* g_pa = (const float4*)(pan  + pb);
    const float4* g_na = (const float4*)(nanp + pb);
    float4* o_sp = (float4*)(spo    + pb);
    float4* o_pa = (float4*)(pao    + pb);
    float4* o_na = (float4*)(nao    + pb);
    float4* o_st = (float4*)(states + pb);
    const float4 zero4 = make_float4(0.f, 0.f, 0.f, 0.f);

    // ---- Stage: coalesced loads -> smem [step i][chunk], pitch 34.
    #pragma unroll
    for (int j = 0; j < 4; j++) {
        int f = j * 32 + lane;
        float4 vs = g_sp[f], vp = g_pa[f], vn = g_na[f];
        o_sp[f] = vs; o_pa[f] = vp; o_na[f] = vn; o_st[f] = zero4;
        int cih = j * 8 + (lane >> 2);
        int i0  = (lane & 3) << 2;
        s_sp[(i0+0)*SIN_PITCH + cih] = vs.x; s_sp[(i0+1)*SIN_PITCH + cih] = vs.y;
        s_sp[(i0+2)*SIN_PITCH + cih] = vs.z; s_sp[(i0+3)*SIN_PITCH + cih] = vs.w;
        s_pa[(i0+0)*SIN_PITCH + cih] = vp.x; s_pa[(i0+1)*SIN_PITCH + cih] = vp.y;
        s_pa[(i0+2)*SIN_PITCH + cih] = vp.z; s_pa[(i0+3)*SIN_PITCH + cih] = vp.w;
        s_na[(i0+0)*SIN_PITCH + cih] = vn.x; s_na[(i0+1)*SIN_PITCH + cih] = vn.y;
        s_na[(i0+2)*SIN_PITCH + cih] = vn.z; s_na[(i0+3)*SIN_PITCH + cih] = vn.w;
    }
    __syncwarp();

    // ---- Pass 1: 16-step chunk transform; d_i overwrites consumed inputs ------
    // Slot [i*34+lane] is only ever read/written by this lane (own column):
    // read(step i) -> write(d_i) within the same iteration is race-free.
    float a0=1.f,a1=0.f,a2=0.f, b0=0.f,b1=1.f,b2=0.f, c0=0.f,c1=0.f,c2=1.f;
    float d0=0.f,d1=0.f,d2=0.f;
    #pragma unroll 4
    for (int i = 0; i < LCH; i++) {
        float pa = s_pa[i*SIN_PITCH + lane];
        float na = s_na[i*SIN_PITCH + lane];
        float sp = s_sp[i*SIN_PITCH + lane];
        frame_step(pa, na, a0,a1,a2,b0,b1,b2,c0,c1,c2);
        d0 = fmaf(sp,a0,d0); d1 = fmaf(sp,a1,d1); d2 = fmaf(sp,a2,d2);
        s_sp[i*SIN_PITCH + lane] = d0;
        s_pa[i*SIN_PITCH + lane] = d1;
        s_na[i*SIN_PITCH + lane] = d2;
    }

    float v[12] = {a0,a1,a2, b0,b1,b2, c0,c1,c2, d0,d1,d2};

    // ---- Intra-warp inclusive scan (affine composition) -----------------------
    #pragma unroll
    for (int off = 1; off <= 16; off <<= 1) {
        float o[12];
        #pragma unroll
        for (int i = 0; i < 12; i++)
            o[i] = __shfl_up_sync(0xffffffffu, v[i], off);
        if (lane >= off) {
            float t[12];
            compose(o, v, t);
            #pragma unroll
            for (int i = 0; i < 12; i++) v[i] = t[i];
        }
    }

    // Half-0 publishes its total (lane 31 inclusive) for half-1.
    if (h == 0 && lane == 31) {
        #pragma unroll
        for (int i = 0; i < 12; i++) glue[i] = v[i];
    }
    __syncthreads();

    // Exclusive prefix within warp.
    float e[12];
    #pragma unroll
    for (int i = 0; i < 12; i++)
        e[i] = __shfl_up_sync(0xffffffffu, v[i], 1);
    if (lane == 0) {
        e[0]=1.f; e[1]=0.f; e[2]=0.f;
        e[3]=0.f; e[4]=1.f; e[5]=0.f;
        e[6]=0.f; e[7]=0.f; e[8]=1.f;
        e[9]=0.f; e[10]=0.f; e[11]=0.f;
    }
    // Half-1: prepend half-0's total.
    if (h == 1) {
        float T0[12];
        #pragma unroll
        for (int i = 0; i < 12; i++) T0[i] = glue[i];
        float t[12];
        compose(T0, e, t);
        #pragma unroll
        for (int i = 0; i < 12; i++) e[i] = t[i];
    }

    // ---- Glue with particle initial frame/pos ----------------------------------
    float A0=e0i[p*3+0], A1=e0i[p*3+1], A2=e0i[p*3+2];
    float B0=e1i[p*3+0], B1=e1i[p*3+1], B2=e1i[p*3+2];
    float C0=e2i[p*3+0], C1=e2i[p*3+1], C2=e2i[p*3+2];
    float x =x0 [p*3+0], y =x0 [p*3+1], z =x0 [p*3+2];

    a0 = fmaf(e[0],A0, fmaf(e[1],B0, e[2]*C0));
    a1 = fmaf(e[0],A1, fmaf(e[1],B1, e[2]*C1));
    a2 = fmaf(e[0],A2, fmaf(e[1],B2, e[2]*C2));
    b0 = fmaf(e[3],A0, fmaf(e[4],B0, e[5]*C0));
    b1 = fmaf(e[3],A1, fmaf(e[4],B1, e[5]*C1));
    b2 = fmaf(e[3],A2, fmaf(e[4],B2, e[5]*C2));
    c0 = fmaf(e[6],A0, fmaf(e[7],B0, e[8]*C0));
    c1 = fmaf(e[6],A1, fmaf(e[7],B1, e[8]*C1));
    c2 = fmaf(e[6],A2, fmaf(e[7],B2, e[8]*C2));
    x  = fmaf(e[9],A0, fmaf(e[10],B0, fmaf(e[11],C0, x)));
    y  = fmaf(e[9],A1, fmaf(e[10],B1, fmaf(e[11],C1, y)));
    z  = fmaf(e[9],A2, fmaf(e[10],B2, fmaf(e[11],C2, z)));

    // Gram-Schmidt renorm (kills composition drift).
    {
        float inv = rsqrtf(fmaf(a0,a0, fmaf(a1,a1, a2*a2)));
        a0*=inv; a1*=inv; a2*=inv;
        float dd = fmaf(b0,a0, fmaf(b1,a1, b2*a2));
        b0 = fmaf(-dd,a0,b0); b1 = fmaf(-dd,a1,b1); b2 = fmaf(-dd,a2,b2);
        inv = rsqrtf(fmaf(b0,b0, fmaf(b1,b1, b2*b2)));
        b0*=inv; b1*=inv; b2*=inv;
        c0 = a1*b2 - a2*b1;
        c1 = a2*b0 - a0*b2;
        c2 = a0*b1 - a1*b0;
    }

    // ---- Pass 2: x_i = x_start + d_i . E_start (9 FMA/step), in place ----------
    // (a,b,c) columns = e0,e1,e2 global vectors at chunk start; d_i is in the
    // chunk-start basis, so component k of x_i = x_k + d0*a_k + d1*b_k + d2*c_k.
    #pragma unroll
    for (int i = 0; i < LCH; i++) {
        float dd0 = s_sp[i*SIN_PITCH + lane];
        float dd1 = s_pa[i*SIN_PITCH + lane];
        float dd2 = s_na[i*SIN_PITCH + lane];
        s_sp[i*SIN_PITCH + lane] = fmaf(dd0,a0, fmaf(dd1,b0, fmaf(dd2,c0, x)));
        s_pa[i*SIN_PITCH + lane] = fmaf(dd0,a1, fmaf(dd1,b1, fmaf(dd2,c1, y)));
        s_na[i*SIN_PITCH + lane] = fmaf(dd0,a2, fmaf(dd1,b2, fmaf(dd2,c2, z)));
    }
    __syncwarp();

    // ---- Flush X: warp's half = 1536 consecutive floats = 384 float4. ----------
    // Element e (0..1535) = own*48 + i*3 + comp, stored in array 'comp' at
    // [i*34 + own]. Gather 4 elements per lane, store one float4 (coalesced).
    float4* gX = (float4*)(X + (size_t)p * 3 * N + (size_t)h * 1536);
    #pragma unroll
    for (int j = 0; j < 12; j++) {
        int L4 = j * 32 + lane;
        float r[4];
        #pragma unroll
        for (int k = 0; k < 4; k++) {
            int ek   = 4 * L4 + k;
            int own  = ek / 48;
            int rem  = ek - own * 48;
            int i    = rem / 3;
            int comp = rem - i * 3;
            const float* arr = (comp == 0) ? s_sp : (comp == 1) ? s_pa : s_na;
            r[k] = arr[i * SIN_PITCH + own];
        }
        gX[L4] = make_float4(r[0], r[1], r[2], r[3]);
    }
}

// ---------------------------------------------------------------------------
// Fallback (proven round-2 path) for unexpected shapes.
// ---------------------------------------------------------------------------
#define PPB 32
#define TT  32
#define SPITCH 33

__global__ void __launch_bounds__(PPB)
explorer_kernel(const float* __restrict__ x0, const float* __restrict__ e0i,
                const float* __restrict__ e1i, const float* __restrict__ e2i,
                const float* __restrict__ spd, const float* __restrict__ pan,
                const float* __restrict__ nan_, float* __restrict__ X,
                int B, int N)
{
    __shared__ float s_sp[TT][SPITCH];
    __shared__ float s_pa[TT][SPITCH];
    __shared__ float s_na[TT][SPITCH];
    __shared__ float s_X[3 * TT][SPITCH];

    const int lane  = threadIdx.x;
    const int pbase = blockIdx.x * PPB;
    const int p     = pbase + lane;
    const bool act  = (p < B);

    float a0=1.f,a1=0.f,a2=0.f, b0=0.f,b1=1.f,b2=0.f, c0=0.f,c1=0.f,c2=1.f;
    float x=0.f, y=0.f, z=0.f;
    if (act) {
        a0=e0i[p*3+0]; a1=e0i[p*3+1]; a2=e0i[p*3+2];
        b0=e1i[p*3+0]; b1=e1i[p*3+1]; b2=e1i[p*3+2];
        c0=e2i[p*3+0]; c1=e2i[p*3+1]; c2=e2i[p*3+2];
        x =x0 [p*3+0]; y =x0 [p*3+1]; z =x0 [p*3+2];
    }

    for (int t0 = 0; t0 < N; t0 += TT) {
        #pragma unroll
        for (int k = 0; k < PPB; k++) {
            int gp = pbase + k;
            float vs=0.f, vp=0.f, vn=0.f;
            if (gp < B && t0 + lane < N) {
                size_t gidx = (size_t)gp * N + (size_t)t0 + lane;
                vs = spd[gidx]; vp = pan[gidx]; vn = nan_[gidx];
            }
            s_sp[lane][k]=vs; s_pa[lane][k]=vp; s_na[lane][k]=vn;
        }
        __syncthreads();

        if (act) {
            int nt = (N - t0 < TT) ? (N - t0) : TT;
            for (int tt = 0; tt < nt; tt++) {
                frame_step(s_pa[tt][lane], s_na[tt][lane],
                           a0,a1,a2,b0,b1,b2,c0,c1,c2);
                float s = s_sp[tt][lane];
                x = fmaf(s,a0,x); y = fmaf(s,a1,y); z = fmaf(s,a2,z);
                s_X[3*tt+0][lane]=x; s_X[3*tt+1][lane]=y; s_X[3*tt+2][lane]=z;
            }
            float inv = rsqrtf(fmaf(a0,a0, fmaf(a1,a1, a2*a2)));
            a0*=inv; a1*=inv; a2*=inv;
            float d = fmaf(b0,a0, fmaf(b1,a1, b2*a2));
            b0=fmaf(-d,a0,b0); b1=fmaf(-d,a1,b1); b2=fmaf(-d,a2,b2);
            inv = rsqrtf(fmaf(b0,b0, fmaf(b1,b1, b2*b2)));
            b0*=inv; b1*=inv; b2*=inv;
            c0=a1*b2-a2*b1; c1=a2*b0-a0*b2; c2=a0*b1-a1*b0;
        }
        __syncthreads();

        #pragma unroll
        for (int k = 0; k < PPB; k++) {
            int gp = pbase + k;
            if (gp < B) {
                size_t bidx = (size_t)gp*3*N + (size_t)t0*3;
                #pragma unroll
                for (int chn = 0; chn < 3; chn++)
                    if (t0*3 + chn*32 + lane < 3*N)
                        X[bidx + chn*32 + lane] = s_X[chn*32 + lane][k];
            }
        }
    }
}

__global__ void ts_kernel(float* __restrict__ ts, int N, const int* __restrict__ dtp)
{
    int i = blockIdx.x * blockDim.x + threadIdx.x;
    if (i >= N) return;
    float dtf = 1.0f;
    if (dtp != nullptr) {
        int v = dtp[0];
        if (v >= 1 && v <= 1000000) dtf = (float)v;
        else { float f = __int_as_float(v); if (f > 0.0f && f < 1.0e6f) dtf = f; }
    }
    ts[i] = (float)i * dtf;
}

// ---------------------------------------------------------------------------
extern "C" void kernel_launch(void* const* d_in, const int* in_sizes, int n_in,
                              void* d_out, int out_size)
{
    const float* x0   = (const float*)d_in[0];
    const float* e0   = (const float*)d_in[1];
    const float* e1   = (const float*)d_in[2];
    const float* e2   = (const float*)d_in[3];
    const float* spd  = (const float*)d_in[4];
    const float* pan  = (const float*)d_in[5];
    const float* nan_ = (const float*)d_in[6];

    const int B = in_sizes[0] / 3;
    const int N = (int)((long long)in_sizes[4] / B);

    float* out    = (float*)d_out;
    float* ts     = out;
    float* X      = out + N;
    float* states = X + (size_t)3 * B * N;
    float* sp_o   = states + (size_t)B * N;
    float* pa_o   = sp_o   + (size_t)B * N;
    float* na_o   = pa_o   + (size_t)B * N;

    const int* dtp = (n_in > 8) ? (const int*)d_in[8] : nullptr;

    const size_t smem_bytes = (size_t)SMEM_FLOATS * sizeof(float);  // ~52.5 KB
    const bool fast = (N == 1024) && (B % 4 == 0);

    if (fast) {
        cudaFuncSetAttribute(fused_kernel,
                             cudaFuncAttributeMaxDynamicSharedMemorySize,
                             (int)smem_bytes);
        fused_kernel<<<B / 4, THREADS, smem_bytes>>>(
            x0, e0, e1, e2, spd, pan, nan_,
            ts, X, states, sp_o, pa_o, na_o, dtp, B, N);
    } else {
        const size_t bn_bytes = (size_t)B * N * sizeof(float);
        explorer_kernel<<<(B + PPB - 1) / PPB, PPB>>>(x0, e0, e1, e2,
                                                      spd, pan, nan_, X, B, N);
        ts_kernel<<<(N + 255) / 256, 256>>>(ts, N, dtp);
        cudaMemsetAsync(states, 0, bn_bytes, 0);
        cudaMemcpyAsync(sp_o, d_in[4], bn_bytes, cudaMemcpyDeviceToDevice, 0);
        cudaMemcpyAsync(pa_o, d_in[5], bn_bytes, cudaMemcpyDeviceToDevice, 0);
        cudaMemcpyAsync(na_o, d_in[6], bn_bytes, cudaMemcpyDeviceToDevice, 0);
    }

    (void)out_size; (void)n_in;
}

// round 11
// speedup vs baseline: 1.2437x; 1.1214x over previous
#include <cuda_runtime.h>
#include <cstdint>

// ---------------------------------------------------------------------------
// ParticleExplorer — fused time-parallel kernel, L=16 chunks, 2 warps/particle,
// in-place smem reuse; pass 2 = 9-FMA matvec; flush uses x3-periodic addressing.
// Per step: E <- E * Rz(pa) * Ry(na);  x <- x + sp * E.col0
// N = 1024 = 64 chunks x 16 steps. Block = 8 warps = 4 particles.
// Output: ts[N] | X[B][N][3] | states[B][N]=0 | speeds | pa | na
// ---------------------------------------------------------------------------

#define LCH 16
#define NWARP 8
#define THREADS (NWARP * 32)

#define SIN_PITCH 34
#define SIN_W (LCH * SIN_PITCH)                       // 544 floats per array
#define GLUE_OFF (NWARP * (3 * SIN_W))                // 13056
#define SMEM_FLOATS (GLUE_OFF + 4 * 16)               // + glue (4 particles x 16)

__device__ __forceinline__ void frame_step(float pa, float na,
    float& a0, float& a1, float& a2,
    float& b0, float& b1, float& b2,
    float& c0, float& c1, float& c2)
{
    float s1, cc1, s2, cc2;
    __sincosf(pa, &s1, &cc1);
    __sincosf(na, &s2, &cc2);
    float p00 = cc1 * cc2, p10 = s1 * cc2;
    float p02 = cc1 * s2,  p12 = s1 * s2;

    float na0 = fmaf(p00, a0, fmaf(p10, b0, -s2 * c0));
    float na1 = fmaf(p00, a1, fmaf(p10, b1, -s2 * c1));
    float na2 = fmaf(p00, a2, fmaf(p10, b2, -s2 * c2));
    float nb0 = fmaf(cc1, b0, -s1 * a0);
    float nb1 = fmaf(cc1, b1, -s1 * a1);
    float nb2 = fmaf(cc1, b2, -s1 * a2);
    float nc0 = fmaf(p02, a0, fmaf(p12, b0, cc2 * c0));
    float nc1 = fmaf(p02, a1, fmaf(p12, b1, cc2 * c1));
    float nc2 = fmaf(p02, a2, fmaf(p12, b2, cc2 * c2));
    a0 = na0; a1 = na1; a2 = na2;
    b0 = nb0; b1 = nb1; b2 = nb2;
    c0 = nc0; c1 = nc1; c2 = nc2;
}

// Affine compose: r earlier, q later (coeffs in r's start basis).
__device__ __forceinline__ void compose(const float* __restrict__ r,
                                        const float* __restrict__ q,
                                        float* __restrict__ o)
{
    #pragma unroll
    for (int col = 0; col < 3; col++) {
        float q0 = q[col*3+0], q1 = q[col*3+1], q2 = q[col*3+2];
        o[col*3+0] = fmaf(q0, r[0], fmaf(q1, r[3], q2 * r[6]));
        o[col*3+1] = fmaf(q0, r[1], fmaf(q1, r[4], q2 * r[7]));
        o[col*3+2] = fmaf(q0, r[2], fmaf(q1, r[5], q2 * r[8]));
    }
    float d0 = q[9], d1 = q[10], d2 = q[11];
    o[9]  = fmaf(d0, r[0], fmaf(d1, r[3], fmaf(d2, r[6], r[9])));
    o[10] = fmaf(d0, r[1], fmaf(d1, r[4], fmaf(d2, r[7], r[10])));
    o[11] = fmaf(d0, r[2], fmaf(d1, r[5], fmaf(d2, r[8], r[11])));
}

__global__ void __launch_bounds__(THREADS)
fused_kernel(const float* __restrict__ x0, const float* __restrict__ e0i,
             const float* __restrict__ e1i, const float* __restrict__ e2i,
             const float* __restrict__ spd, const float* __restrict__ pan,
             const float* __restrict__ nanp,
             float* __restrict__ ts, float* __restrict__ X,
             float* __restrict__ states, float* __restrict__ spo,
             float* __restrict__ pao, float* __restrict__ nao,
             const int* __restrict__ dtp, int B, int N)
{
    extern __shared__ float sm[];

    const int tid  = threadIdx.x;
    const int lane = tid & 31;
    const int w    = tid >> 5;
    const int h    = w & 1;                 // half (0: steps 0..511, 1: 512..1023)
    const int ps   = w >> 1;                // particle slot in block
    const int p    = blockIdx.x * 4 + ps;
    const int gtid = blockIdx.x * THREADS + tid;

    if (gtid < N) {
        float dtf = 1.0f;
        if (dtp) {
            int vdt = dtp[0];
            if (vdt >= 1 && vdt <= 1000000) dtf = (float)vdt;
            else { float f = __int_as_float(vdt); if (f > 0.f && f < 1.0e6f) dtf = f; }
        }
        ts[gtid] = (float)gtid * dtf;
    }
    // No early return: __syncthreads below needs all threads (grid == B/4 exact).

    float* s_sp = sm + w * (3 * SIN_W);
    float* s_pa = s_sp + SIN_W;
    float* s_na = s_sp + 2 * SIN_W;
    float* glue = sm + GLUE_OFF + ps * 16;

    const size_t pb = (size_t)p * N + (size_t)h * 512;
    const float4* g_sp = (const float4*)(spd  + pb);
    const float4* g_pa = (const float4*)(pan  + pb);
    const float4* g_na = (const float4*)(nanp + pb);
    float4* o_sp = (float4*)(spo    + pb);
    float4* o_pa = (float4*)(pao    + pb);
    float4* o_na = (float4*)(nao    + pb);
    float4* o_st = (float4*)(states + pb);
    const float4 zero4 = make_float4(0.f, 0.f, 0.f, 0.f);

    // ---- Stage: coalesced loads -> smem [step i][chunk], pitch 34.
    #pragma unroll
    for (int j = 0; j < 4; j++) {
        int f = j * 32 + lane;
        float4 vs = g_sp[f], vp = g_pa[f], vn = g_na[f];
        o_sp[f] = vs; o_pa[f] = vp; o_na[f] = vn; o_st[f] = zero4;
        int cih = j * 8 + (lane >> 2);
        int i0  = (lane & 3) << 2;
        s_sp[(i0+0)*SIN_PITCH + cih] = vs.x; s_sp[(i0+1)*SIN_PITCH + cih] = vs.y;
        s_sp[(i0+2)*SIN_PITCH + cih] = vs.z; s_sp[(i0+3)*SIN_PITCH + cih] = vs.w;
        s_pa[(i0+0)*SIN_PITCH + cih] = vp.x; s_pa[(i0+1)*SIN_PITCH + cih] = vp.y;
        s_pa[(i0+2)*SIN_PITCH + cih] = vp.z; s_pa[(i0+3)*SIN_PITCH + cih] = vp.w;
        s_na[(i0+0)*SIN_PITCH + cih] = vn.x; s_na[(i0+1)*SIN_PITCH + cih] = vn.y;
        s_na[(i0+2)*SIN_PITCH + cih] = vn.z; s_na[(i0+3)*SIN_PITCH + cih] = vn.w;
    }
    __syncwarp();

    // ---- Pass 1: 16-step chunk transform; d_i overwrites consumed inputs ------
    float a0=1.f,a1=0.f,a2=0.f, b0=0.f,b1=1.f,b2=0.f, c0=0.f,c1=0.f,c2=1.f;
    float d0=0.f,d1=0.f,d2=0.f;
    #pragma unroll 4
    for (int i = 0; i < LCH; i++) {
        float pa = s_pa[i*SIN_PITCH + lane];
        float na = s_na[i*SIN_PITCH + lane];
        float sp = s_sp[i*SIN_PITCH + lane];
        frame_step(pa, na, a0,a1,a2,b0,b1,b2,c0,c1,c2);
        d0 = fmaf(sp,a0,d0); d1 = fmaf(sp,a1,d1); d2 = fmaf(sp,a2,d2);
        s_sp[i*SIN_PITCH + lane] = d0;
        s_pa[i*SIN_PITCH + lane] = d1;
        s_na[i*SIN_PITCH + lane] = d2;
    }

    float v[12] = {a0,a1,a2, b0,b1,b2, c0,c1,c2, d0,d1,d2};

    // ---- Intra-warp inclusive scan (affine composition) -----------------------
    #pragma unroll
    for (int off = 1; off <= 16; off <<= 1) {
        float o[12];
        #pragma unroll
        for (int i = 0; i < 12; i++)
            o[i] = __shfl_up_sync(0xffffffffu, v[i], off);
        if (lane >= off) {
            float t[12];
            compose(o, v, t);
            #pragma unroll
            for (int i = 0; i < 12; i++) v[i] = t[i];
        }
    }

    // Half-0 publishes its total (lane 31 inclusive) for half-1.
    if (h == 0 && lane == 31) {
        #pragma unroll
        for (int i = 0; i < 12; i++) glue[i] = v[i];
    }
    __syncthreads();

    // Exclusive prefix within warp.
    float e[12];
    #pragma unroll
    for (int i = 0; i < 12; i++)
        e[i] = __shfl_up_sync(0xffffffffu, v[i], 1);
    if (lane == 0) {
        e[0]=1.f; e[1]=0.f; e[2]=0.f;
        e[3]=0.f; e[4]=1.f; e[5]=0.f;
        e[6]=0.f; e[7]=0.f; e[8]=1.f;
        e[9]=0.f; e[10]=0.f; e[11]=0.f;
    }
    // Half-1: prepend half-0's total.
    if (h == 1) {
        float T0[12];
        #pragma unroll
        for (int i = 0; i < 12; i++) T0[i] = glue[i];
        float t[12];
        compose(T0, e, t);
        #pragma unroll
        for (int i = 0; i < 12; i++) e[i] = t[i];
    }

    // ---- Glue with particle initial frame/pos ----------------------------------
    float A0=e0i[p*3+0], A1=e0i[p*3+1], A2=e0i[p*3+2];
    float B0=e1i[p*3+0], B1=e1i[p*3+1], B2=e1i[p*3+2];
    float C0=e2i[p*3+0], C1=e2i[p*3+1], C2=e2i[p*3+2];
    float x =x0 [p*3+0], y =x0 [p*3+1], z =x0 [p*3+2];

    a0 = fmaf(e[0],A0, fmaf(e[1],B0, e[2]*C0));
    a1 = fmaf(e[0],A1, fmaf(e[1],B1, e[2]*C1));
    a2 = fmaf(e[0],A2, fmaf(e[1],B2, e[2]*C2));
    b0 = fmaf(e[3],A0, fmaf(e[4],B0, e[5]*C0));
    b1 = fmaf(e[3],A1, fmaf(e[4],B1, e[5]*C1));
    b2 = fmaf(e[3],A2, fmaf(e[4],B2, e[5]*C2));
    c0 = fmaf(e[6],A0, fmaf(e[7],B0, e[8]*C0));
    c1 = fmaf(e[6],A1, fmaf(e[7],B1, e[8]*C1));
    c2 = fmaf(e[6],A2, fmaf(e[7],B2, e[8]*C2));
    x  = fmaf(e[9],A0, fmaf(e[10],B0, fmaf(e[11],C0, x)));
    y  = fmaf(e[9],A1, fmaf(e[10],B1, fmaf(e[11],C1, y)));
    z  = fmaf(e[9],A2, fmaf(e[10],B2, fmaf(e[11],C2, z)));

    // Gram-Schmidt renorm (kills composition drift).
    {
        float inv = rsqrtf(fmaf(a0,a0, fmaf(a1,a1, a2*a2)));
        a0*=inv; a1*=inv; a2*=inv;
        float dd = fmaf(b0,a0, fmaf(b1,a1, b2*a2));
        b0 = fmaf(-dd,a0,b0); b1 = fmaf(-dd,a1,b1); b2 = fmaf(-dd,a2,b2);
        inv = rsqrtf(fmaf(b0,b0, fmaf(b1,b1, b2*b2)));
        b0*=inv; b1*=inv; b2*=inv;
        c0 = a1*b2 - a2*b1;
        c1 = a2*b0 - a0*b2;
        c2 = a0*b1 - a1*b0;
    }

    // ---- Pass 2: x_i = x_start + d_i . E_start (9 FMA/step), in place ----------
    #pragma unroll
    for (int i = 0; i < LCH; i++) {
        float dd0 = s_sp[i*SIN_PITCH + lane];
        float dd1 = s_pa[i*SIN_PITCH + lane];
        float dd2 = s_na[i*SIN_PITCH + lane];
        s_sp[i*SIN_PITCH + lane] = fmaf(dd0,a0, fmaf(dd1,b0, fmaf(dd2,c0, x)));
        s_pa[i*SIN_PITCH + lane] = fmaf(dd0,a1, fmaf(dd1,b1, fmaf(dd2,c1, y)));
        s_na[i*SIN_PITCH + lane] = fmaf(dd0,a2, fmaf(dd1,b2, fmaf(dd2,c2, z)));
    }
    __syncwarp();

    // ---- Flush X: 384 float4 per warp-half, x3-periodic addressing. ------------
    // Element ek = 128j + 4*lane + k maps to (own=ek/48, i=(ek%48)/3, comp=ek%3),
    // stored in array 'comp' at [i*34 + own]. Since j->j+3 adds 384 = 8*48,
    // (i, comp) are invariant and own += 8: compute the 12 classes once
    // (j=0,1,2 x k=0..3), reuse with immediate +8m offsets for j=3..11.
    float4* gX = (float4*)(X + (size_t)p * 3 * N + (size_t)h * 1536);
    #pragma unroll
    for (int jc = 0; jc < 3; jc++) {
        const float* arr[4];
        int addr[4];
        #pragma unroll
        for (int k = 0; k < 4; k++) {
            int ek   = 128 * jc + 4 * lane + k;
            int own  = ek / 48;
            int rem  = ek - own * 48;
            int i    = rem / 3;
            int comp = rem - i * 3;
            arr[k]  = (comp == 0) ? s_sp : (comp == 1) ? s_pa : s_na;
            addr[k] = i * SIN_PITCH + own;
        }
        #pragma unroll
        for (int m = 0; m < 4; m++) {
            int j = jc + 3 * m;
            float4 r;
            r.x = arr[0][addr[0] + 8 * m];
            r.y = arr[1][addr[1] + 8 * m];
            r.z = arr[2][addr[2] + 8 * m];
            r.w = arr[3][addr[3] + 8 * m];
            gX[j * 32 + lane] = r;
        }
    }
}

// ---------------------------------------------------------------------------
// Fallback (proven round-2 path) for unexpected shapes.
// ---------------------------------------------------------------------------
#define PPB 32
#define TT  32
#define SPITCH 33

__global__ void __launch_bounds__(PPB)
explorer_kernel(const float* __restrict__ x0, const float* __restrict__ e0i,
                const float* __restrict__ e1i, const float* __restrict__ e2i,
                const float* __restrict__ spd, const float* __restrict__ pan,
                const float* __restrict__ nan_, float* __restrict__ X,
                int B, int N)
{
    __shared__ float s_sp[TT][SPITCH];
    __shared__ float s_pa[TT][SPITCH];
    __shared__ float s_na[TT][SPITCH];
    __shared__ float s_X[3 * TT][SPITCH];

    const int lane  = threadIdx.x;
    const int pbase = blockIdx.x * PPB;
    const int p     = pbase + lane;
    const bool act  = (p < B);

    float a0=1.f,a1=0.f,a2=0.f, b0=0.f,b1=1.f,b2=0.f, c0=0.f,c1=0.f,c2=1.f;
    float x=0.f, y=0.f, z=0.f;
    if (act) {
        a0=e0i[p*3+0]; a1=e0i[p*3+1]; a2=e0i[p*3+2];
        b0=e1i[p*3+0]; b1=e1i[p*3+1]; b2=e1i[p*3+2];
        c0=e2i[p*3+0]; c1=e2i[p*3+1]; c2=e2i[p*3+2];
        x =x0 [p*3+0]; y =x0 [p*3+1]; z =x0 [p*3+2];
    }

    for (int t0 = 0; t0 < N; t0 += TT) {
        #pragma unroll
        for (int k = 0; k < PPB; k++) {
            int gp = pbase + k;
            float vs=0.f, vp=0.f, vn=0.f;
            if (gp < B && t0 + lane < N) {
                size_t gidx = (size_t)gp * N + (size_t)t0 + lane;
                vs = spd[gidx]; vp = pan[gidx]; vn = nan_[gidx];
            }
            s_sp[lane][k]=vs; s_pa[lane][k]=vp; s_na[lane][k]=vn;
        }
        __syncthreads();

        if (act) {
            int nt = (N - t0 < TT) ? (N - t0) : TT;
            for (int tt = 0; tt < nt; tt++) {
                frame_step(s_pa[tt][lane], s_na[tt][lane],
                           a0,a1,a2,b0,b1,b2,c0,c1,c2);
                float s = s_sp[tt][lane];
                x = fmaf(s,a0,x); y = fmaf(s,a1,y); z = fmaf(s,a2,z);
                s_X[3*tt+0][lane]=x; s_X[3*tt+1][lane]=y; s_X[3*tt+2][lane]=z;
            }
            float inv = rsqrtf(fmaf(a0,a0, fmaf(a1,a1, a2*a2)));
            a0*=inv; a1*=inv; a2*=inv;
            float d = fmaf(b0,a0, fmaf(b1,a1, b2*a2));
            b0=fmaf(-d,a0,b0); b1=fmaf(-d,a1,b1); b2=fmaf(-d,a2,b2);
            inv = rsqrtf(fmaf(b0,b0, fmaf(b1,b1, b2*b2)));
            b0*=inv; b1*=inv; b2*=inv;
            c0=a1*b2-a2*b1; c1=a2*b0-a0*b2; c2=a0*b1-a1*b0;
        }
        __syncthreads();

        #pragma unroll
        for (int k = 0; k < PPB; k++) {
            int gp = pbase + k;
            if (gp < B) {
                size_t bidx = (size_t)gp*3*N + (size_t)t0*3;
                #pragma unroll
                for (int chn = 0; chn < 3; chn++)
                    if (t0*3 + chn*32 + lane < 3*N)
                        X[bidx + chn*32 + lane] = s_X[chn*32 + lane][k];
            }
        }
    }
}

__global__ void ts_kernel(float* __restrict__ ts, int N, const int* __restrict__ dtp)
{
    int i = blockIdx.x * blockDim.x + threadIdx.x;
    if (i >= N) return;
    float dtf = 1.0f;
    if (dtp != nullptr) {
        int v = dtp[0];
        if (v >= 1 && v <= 1000000) dtf = (float)v;
        else { float f = __int_as_float(v); if (f > 0.0f && f < 1.0e6f) dtf = f; }
    }
    ts[i] = (float)i * dtf;
}

// ---------------------------------------------------------------------------
extern "C" void kernel_launch(void* const* d_in, const int* in_sizes, int n_in,
                              void* d_out, int out_size)
{
    const float* x0   = (const float*)d_in[0];
    const float* e0   = (const float*)d_in[1];
    const float* e1   = (const float*)d_in[2];
    const float* e2   = (const float*)d_in[3];
    const float* spd  = (const float*)d_in[4];
    const float* pan  = (const float*)d_in[5];
    const float* nan_ = (const float*)d_in[6];

    const int B = in_sizes[0] / 3;
    const int N = (int)((long long)in_sizes[4] / B);

    float* out    = (float*)d_out;
    float* ts     = out;
    float* X      = out + N;
    float* states = X + (size_t)3 * B * N;
    float* sp_o   = states + (size_t)B * N;
    float* pa_o   = sp_o   + (size_t)B * N;
    float* na_o   = pa_o   + (size_t)B * N;

    const int* dtp = (n_in > 8) ? (const int*)d_in[8] : nullptr;

    const size_t smem_bytes = (size_t)SMEM_FLOATS * sizeof(float);  // ~52.5 KB
    const bool fast = (N == 1024) && (B % 4 == 0);

    if (fast) {
        cudaFuncSetAttribute(fused_kernel,
                             cudaFuncAttributeMaxDynamicSharedMemorySize,
                             (int)smem_bytes);
        fused_kernel<<<B / 4, THREADS, smem_bytes>>>(
            x0, e0, e1, e2, spd, pan, nan_,
            ts, X, states, sp_o, pa_o, na_o, dtp, B, N);
    } else {
        const size_t bn_bytes = (size_t)B * N * sizeof(float);
        explorer_kernel<<<(B + PPB - 1) / PPB, PPB>>>(x0, e0, e1, e2,
                                                      spd, pan, nan_, X, B, N);
        ts_kernel<<<(N + 255) / 256, 256>>>(ts, N, dtp);
        cudaMemsetAsync(states, 0, bn_bytes, 0);
        cudaMemcpyAsync(sp_o, d_in[4], bn_bytes, cudaMemcpyDeviceToDevice, 0);
        cudaMemcpyAsync(pa_o, d_in[5], bn_bytes, cudaMemcpyDeviceToDevice, 0);
        cudaMemcpyAsync(na_o, d_in[6], bn_bytes, cudaMemcpyDeviceToDevice, 0);
    }

    (void)out_size; (void)n_in;
}

// round 12
// speedup vs baseline: 1.3285x; 1.0682x over previous
#include <cuda_runtime.h>
#include <cstdint>

// ---------------------------------------------------------------------------
// ParticleExplorer — fused time-parallel kernel, L=8 chunks, 4 warps/particle.
// Per step: E <- E * Rz(pa) * Ry(na);  x <- x + sp * E.col0
// N = 1024 = 128 chunks x 8 steps. Block = 8 warps = 2 particles.
// Warp w: particle slot w>>2, quarter q = w&3 (chunks q*32+lane).
//   stage : coalesced float4 loads -> smem [step][chunk] pitch-36, aux folded
//   pass 1: 8-step chunk transform; running displacement d_i overwrites inputs
//   scan  : intra-warp shfl scan + 4-way cross-quarter smem glue
//   glue  : compose with (E0,x0), Gram-Schmidt renorm
//   pass 2: x_i = x_start + d_i . E_start (9 FMA/step), in place
//   flush : x3-periodic gather -> coalesced float4 stores
// Output: ts[N] | X[B][N][3] | states[B][N]=0 | speeds | pa | na
// ---------------------------------------------------------------------------

#define LCH 8
#define NWARP 8
#define THREADS (NWARP * 32)

#define SIN_PITCH 36
#define SIN_W (LCH * SIN_PITCH)                       // 288 floats per array
#define GLUE_OFF (NWARP * (3 * SIN_W))                // 6912
#define SMEM_FLOATS (GLUE_OFF + 2 * 48)               // + glue (2 particles x 4x12)

__device__ __forceinline__ void frame_step(float pa, float na,
    float& a0, float& a1, float& a2,
    float& b0, float& b1, float& b2,
    float& c0, float& c1, float& c2)
{
    float s1, cc1, s2, cc2;
    __sincosf(pa, &s1, &cc1);
    __sincosf(na, &s2, &cc2);
    float p00 = cc1 * cc2, p10 = s1 * cc2;
    float p02 = cc1 * s2,  p12 = s1 * s2;

    float na0 = fmaf(p00, a0, fmaf(p10, b0, -s2 * c0));
    float na1 = fmaf(p00, a1, fmaf(p10, b1, -s2 * c1));
    float na2 = fmaf(p00, a2, fmaf(p10, b2, -s2 * c2));
    float nb0 = fmaf(cc1, b0, -s1 * a0);
    float nb1 = fmaf(cc1, b1, -s1 * a1);
    float nb2 = fmaf(cc1, b2, -s1 * a2);
    float nc0 = fmaf(p02, a0, fmaf(p12, b0, cc2 * c0));
    float nc1 = fmaf(p02, a1, fmaf(p12, b1, cc2 * c1));
    float nc2 = fmaf(p02, a2, fmaf(p12, b2, cc2 * c2));
    a0 = na0; a1 = na1; a2 = na2;
    b0 = nb0; b1 = nb1; b2 = nb2;
    c0 = nc0; c1 = nc1; c2 = nc2;
}

// Affine compose: r earlier, q later (coeffs in r's start basis).
__device__ __forceinline__ void compose(const float* __restrict__ r,
                                        const float* __restrict__ q,
                                        float* __restrict__ o)
{
    #pragma unroll
    for (int col = 0; col < 3; col++) {
        float q0 = q[col*3+0], q1 = q[col*3+1], q2 = q[col*3+2];
        o[col*3+0] = fmaf(q0, r[0], fmaf(q1, r[3], q2 * r[6]));
        o[col*3+1] = fmaf(q0, r[1], fmaf(q1, r[4], q2 * r[7]));
        o[col*3+2] = fmaf(q0, r[2], fmaf(q1, r[5], q2 * r[8]));
    }
    float d0 = q[9], d1 = q[10], d2 = q[11];
    o[9]  = fmaf(d0, r[0], fmaf(d1, r[3], fmaf(d2, r[6], r[9])));
    o[10] = fmaf(d0, r[1], fmaf(d1, r[4], fmaf(d2, r[7], r[10])));
    o[11] = fmaf(d0, r[2], fmaf(d1, r[5], fmaf(d2, r[8], r[11])));
}

__global__ void __launch_bounds__(THREADS, 5)
fused_kernel(const float* __restrict__ x0, const float* __restrict__ e0i,
             const float* __restrict__ e1i, const float* __restrict__ e2i,
             const float* __restrict__ spd, const float* __restrict__ pan,
             const float* __restrict__ nanp,
             float* __restrict__ ts, float* __restrict__ X,
             float* __restrict__ states, float* __restrict__ spo,
             float* __restrict__ pao, float* __restrict__ nao,
             const int* __restrict__ dtp, int B, int N)
{
    extern __shared__ float sm[];

    const int tid  = threadIdx.x;
    const int lane = tid & 31;
    const int w    = tid >> 5;
    const int q    = w & 3;                 // quarter of the timeline
    const int ps   = w >> 2;                // particle slot in block (0..1)
    const int p    = blockIdx.x * 2 + ps;
    const int gtid = blockIdx.x * THREADS + tid;

    if (gtid < N) {
        float dtf = 1.0f;
        if (dtp) {
            int vdt = dtp[0];
            if (vdt >= 1 && vdt <= 1000000) dtf = (float)vdt;
            else { float f = __int_as_float(vdt); if (f > 0.f && f < 1.0e6f) dtf = f; }
        }
        ts[gtid] = (float)gtid * dtf;
    }
    // No early return: __syncthreads below needs all threads (grid == B/2 exact).

    float* s_sp = sm + w * (3 * SIN_W);
    float* s_pa = s_sp + SIN_W;
    float* s_na = s_sp + 2 * SIN_W;
    float* glue = sm + GLUE_OFF + ps * 48;   // 4 totals x 12 floats

    const size_t pb = (size_t)p * N + (size_t)q * 256;
    const float4* g_sp = (const float4*)(spd  + pb);
    const float4* g_pa = (const float4*)(pan  + pb);
    const float4* g_na = (const float4*)(nanp + pb);
    float4* o_sp = (float4*)(spo    + pb);
    float4* o_pa = (float4*)(pao    + pb);
    float4* o_na = (float4*)(nao    + pb);
    float4* o_st = (float4*)(states + pb);
    const float4 zero4 = make_float4(0.f, 0.f, 0.f, 0.f);

    // ---- Stage: coalesced loads -> smem [step i][chunk c], pitch 36.
    // Element e = 4f+k (f = j*32+lane): c = e>>3 = 16j + (lane>>1),
    // i = e&7 = 4*(lane&1)+k. Rows {k, k+4}: 4*36 = 144 ≡ 16 (mod 32) ->
    // the two 16-lane address sets are complementary mod 32 (conflict-free).
    #pragma unroll
    for (int j = 0; j < 2; j++) {
        int f = j * 32 + lane;
        float4 vs = g_sp[f], vp = g_pa[f], vn = g_na[f];
        o_sp[f] = vs; o_pa[f] = vp; o_na[f] = vn; o_st[f] = zero4;
        int c  = 16 * j + (lane >> 1);
        int i0 = (lane & 1) << 2;
        s_sp[(i0+0)*SIN_PITCH + c] = vs.x; s_sp[(i0+1)*SIN_PITCH + c] = vs.y;
        s_sp[(i0+2)*SIN_PITCH + c] = vs.z; s_sp[(i0+3)*SIN_PITCH + c] = vs.w;
        s_pa[(i0+0)*SIN_PITCH + c] = vp.x; s_pa[(i0+1)*SIN_PITCH + c] = vp.y;
        s_pa[(i0+2)*SIN_PITCH + c] = vp.z; s_pa[(i0+3)*SIN_PITCH + c] = vp.w;
        s_na[(i0+0)*SIN_PITCH + c] = vn.x; s_na[(i0+1)*SIN_PITCH + c] = vn.y;
        s_na[(i0+2)*SIN_PITCH + c] = vn.z; s_na[(i0+3)*SIN_PITCH + c] = vn.w;
    }
    __syncwarp();

    // ---- Pass 1: 8-step chunk transform; d_i overwrites consumed inputs -------
    float a0=1.f,a1=0.f,a2=0.f, b0=0.f,b1=1.f,b2=0.f, c0=0.f,c1=0.f,c2=1.f;
    float d0=0.f,d1=0.f,d2=0.f;
    #pragma unroll
    for (int i = 0; i < LCH; i++) {
        float pa = s_pa[i*SIN_PITCH + lane];
        float na = s_na[i*SIN_PITCH + lane];
        float sp = s_sp[i*SIN_PITCH + lane];
        frame_step(pa, na, a0,a1,a2,b0,b1,b2,c0,c1,c2);
        d0 = fmaf(sp,a0,d0); d1 = fmaf(sp,a1,d1); d2 = fmaf(sp,a2,d2);
        s_sp[i*SIN_PITCH + lane] = d0;
        s_pa[i*SIN_PITCH + lane] = d1;
        s_na[i*SIN_PITCH + lane] = d2;
    }

    float v[12] = {a0,a1,a2, b0,b1,b2, c0,c1,c2, d0,d1,d2};

    // ---- Intra-warp inclusive scan (affine composition) -----------------------
    #pragma unroll
    for (int off = 1; off <= 16; off <<= 1) {
        float o[12];
        #pragma unroll
        for (int i = 0; i < 12; i++)
            o[i] = __shfl_up_sync(0xffffffffu, v[i], off);
        if (lane >= off) {
            float t[12];
            compose(o, v, t);
            #pragma unroll
            for (int i = 0; i < 12; i++) v[i] = t[i];
        }
    }

    // Publish each quarter's total (lane 31 inclusive).
    if (lane == 31) {
        #pragma unroll
        for (int i = 0; i < 12; i++) glue[q*12 + i] = v[i];
    }
    __syncthreads();

    // Exclusive prefix within warp.
    float e[12];
    #pragma unroll
    for (int i = 0; i < 12; i++)
        e[i] = __shfl_up_sync(0xffffffffu, v[i], 1);
    if (lane == 0) {
        e[0]=1.f; e[1]=0.f; e[2]=0.f;
        e[3]=0.f; e[4]=1.f; e[5]=0.f;
        e[6]=0.f; e[7]=0.f; e[8]=1.f;
        e[9]=0.f; e[10]=0.f; e[11]=0.f;
    }
    // Prepend earlier quarters' totals (lane-redundant smem broadcasts).
    if (q > 0) {
        float P[12];
        #pragma unroll
        for (int i = 0; i < 12; i++) P[i] = glue[i];
        for (int k = 1; k < q; k++) {
            float T[12], t2[12];
            #pragma unroll
            for (int i = 0; i < 12; i++) T[i] = glue[k*12 + i];
            compose(P, T, t2);
            #pragma unroll
            for (int i = 0; i < 12; i++) P[i] = t2[i];
        }
        float t[12];
        compose(P, e, t);
        #pragma unroll
        for (int i = 0; i < 12; i++) e[i] = t[i];
    }

    // ---- Glue with particle initial frame/pos ----------------------------------
    float A0=e0i[p*3+0], A1=e0i[p*3+1], A2=e0i[p*3+2];
    float B0=e1i[p*3+0], B1=e1i[p*3+1], B2=e1i[p*3+2];
    float C0=e2i[p*3+0], C1=e2i[p*3+1], C2=e2i[p*3+2];
    float x =x0 [p*3+0], y =x0 [p*3+1], z =x0 [p*3+2];

    a0 = fmaf(e[0],A0, fmaf(e[1],B0, e[2]*C0));
    a1 = fmaf(e[0],A1, fmaf(e[1],B1, e[2]*C1));
    a2 = fmaf(e[0],A2, fmaf(e[1],B2, e[2]*C2));
    b0 = fmaf(e[3],A0, fmaf(e[4],B0, e[5]*C0));
    b1 = fmaf(e[3],A1, fmaf(e[4],B1, e[5]*C1));
    b2 = fmaf(e[3],A2, fmaf(e[4],B2, e[5]*C2));
    c0 = fmaf(e[6],A0, fmaf(e[7],B0, e[8]*C0));
    c1 = fmaf(e[6],A1, fmaf(e[7],B1, e[8]*C1));
    c2 = fmaf(e[6],A2, fmaf(e[7],B2, e[8]*C2));
    x  = fmaf(e[9],A0, fmaf(e[10],B0, fmaf(e[11],C0, x)));
    y  = fmaf(e[9],A1, fmaf(e[10],B1, fmaf(e[11],C1, y)));
    z  = fmaf(e[9],A2, fmaf(e[10],B2, fmaf(e[11],C2, z)));

    // Gram-Schmidt renorm (kills composition drift).
    {
        float inv = rsqrtf(fmaf(a0,a0, fmaf(a1,a1, a2*a2)));
        a0*=inv; a1*=inv; a2*=inv;
        float dd = fmaf(b0,a0, fmaf(b1,a1, b2*a2));
        b0 = fmaf(-dd,a0,b0); b1 = fmaf(-dd,a1,b1); b2 = fmaf(-dd,a2,b2);
        inv = rsqrtf(fmaf(b0,b0, fmaf(b1,b1, b2*b2)));
        b0*=inv; b1*=inv; b2*=inv;
        c0 = a1*b2 - a2*b1;
        c1 = a2*b0 - a0*b2;
        c2 = a0*b1 - a1*b0;
    }

    // ---- Pass 2: x_i = x_start + d_i . E_start (9 FMA/step), in place ----------
    #pragma unroll
    for (int i = 0; i < LCH; i++) {
        float dd0 = s_sp[i*SIN_PITCH + lane];
        float dd1 = s_pa[i*SIN_PITCH + lane];
        float dd2 = s_na[i*SIN_PITCH + lane];
        s_sp[i*SIN_PITCH + lane] = fmaf(dd0,a0, fmaf(dd1,b0, fmaf(dd2,c0, x)));
        s_pa[i*SIN_PITCH + lane] = fmaf(dd0,a1, fmaf(dd1,b1, fmaf(dd2,c1, y)));
        s_na[i*SIN_PITCH + lane] = fmaf(dd0,a2, fmaf(dd1,b2, fmaf(dd2,c2, z)));
    }
    __syncwarp();

    // ---- Flush X: 192 float4 per warp-quarter, x3-periodic addressing. ---------
    // Element ek = 128j + 4*lane + k -> (own=ek/24, i=(ek%24)/3, comp=ek%3),
    // stored in array 'comp' at [i*36 + own]. j->j+3 adds 384 = 16*24:
    // (i, comp) invariant, own += 16.
    float4* gX = (float4*)(X + (size_t)p * 3 * N + (size_t)q * 768);
    #pragma unroll
    for (int jc = 0; jc < 3; jc++) {
        const float* arr[4];
        int addr[4];
        #pragma unroll
        for (int k = 0; k < 4; k++) {
            int ek   = 128 * jc + 4 * lane + k;
            int own  = ek / 24;
            int rem  = ek - own * 24;
            int i    = rem / 3;
            int comp = rem - i * 3;
            arr[k]  = (comp == 0) ? s_sp : (comp == 1) ? s_pa : s_na;
            addr[k] = i * SIN_PITCH + own;
        }
        #pragma unroll
        for (int m = 0; m < 2; m++) {
            int j = jc + 3 * m;
            float4 r;
            r.x = arr[0][addr[0] + 16 * m];
            r.y = arr[1][addr[1] + 16 * m];
            r.z = arr[2][addr[2] + 16 * m];
            r.w = arr[3][addr[3] + 16 * m];
            gX[j * 32 + lane] = r;
        }
    }
}

// ---------------------------------------------------------------------------
// Fallback (proven round-2 path) for unexpected shapes.
// ---------------------------------------------------------------------------
#define PPB 32
#define TT  32
#define SPITCH 33

__global__ void __launch_bounds__(PPB)
explorer_kernel(const float* __restrict__ x0, const float* __restrict__ e0i,
                const float* __restrict__ e1i, const float* __restrict__ e2i,
                const float* __restrict__ spd, const float* __restrict__ pan,
                const float* __restrict__ nan_, float* __restrict__ X,
                int B, int N)
{
    __shared__ float s_sp[TT][SPITCH];
    __shared__ float s_pa[TT][SPITCH];
    __shared__ float s_na[TT][SPITCH];
    __shared__ float s_X[3 * TT][SPITCH];

    const int lane  = threadIdx.x;
    const int pbase = blockIdx.x * PPB;
    const int p     = pbase + lane;
    const bool act  = (p < B);

    float a0=1.f,a1=0.f,a2=0.f, b0=0.f,b1=1.f,b2=0.f, c0=0.f,c1=0.f,c2=1.f;
    float x=0.f, y=0.f, z=0.f;
    if (act) {
        a0=e0i[p*3+0]; a1=e0i[p*3+1]; a2=e0i[p*3+2];
        b0=e1i[p*3+0]; b1=e1i[p*3+1]; b2=e1i[p*3+2];
        c0=e2i[p*3+0]; c1=e2i[p*3+1]; c2=e2i[p*3+2];
        x =x0 [p*3+0]; y =x0 [p*3+1]; z =x0 [p*3+2];
    }

    for (int t0 = 0; t0 < N; t0 += TT) {
        #pragma unroll
        for (int k = 0; k < PPB; k++) {
            int gp = pbase + k;
            float vs=0.f, vp=0.f, vn=0.f;
            if (gp < B && t0 + lane < N) {
                size_t gidx = (size_t)gp * N + (size_t)t0 + lane;
                vs = spd[gidx]; vp = pan[gidx]; vn = nan_[gidx];
            }
            s_sp[lane][k]=vs; s_pa[lane][k]=vp; s_na[lane][k]=vn;
        }
        __syncthreads();

        if (act) {
            int nt = (N - t0 < TT) ? (N - t0) : TT;
            for (int tt = 0; tt < nt; tt++) {
                frame_step(s_pa[tt][lane], s_na[tt][lane],
                           a0,a1,a2,b0,b1,b2,c0,c1,c2);
                float s = s_sp[tt][lane];
                x = fmaf(s,a0,x); y = fmaf(s,a1,y); z = fmaf(s,a2,z);
                s_X[3*tt+0][lane]=x; s_X[3*tt+1][lane]=y; s_X[3*tt+2][lane]=z;
            }
            float inv = rsqrtf(fmaf(a0,a0, fmaf(a1,a1, a2*a2)));
            a0*=inv; a1*=inv; a2*=inv;
            float d = fmaf(b0,a0, fmaf(b1,a1, b2*a2));
            b0=fmaf(-d,a0,b0); b1=fmaf(-d,a1,b1); b2=fmaf(-d,a2,b2);
            inv = rsqrtf(fmaf(b0,b0, fmaf(b1,b1, b2*b2)));
            b0*=inv; b1*=inv; b2*=inv;
            c0=a1*b2-a2*b1; c1=a2*b0-a0*b2; c2=a0*b1-a1*b0;
        }
        __syncthreads();

        #pragma unroll
        for (int k = 0; k < PPB; k++) {
            int gp = pbase + k;
            if (gp < B) {
                size_t bidx = (size_t)gp*3*N + (size_t)t0*3;
                #pragma unroll
                for (int chn = 0; chn < 3; chn++)
                    if (t0*3 + chn*32 + lane < 3*N)
                        X[bidx + chn*32 + lane] = s_X[chn*32 + lane][k];
            }
        }
    }
}

__global__ void ts_kernel(float* __restrict__ ts, int N, const int* __restrict__ dtp)
{
    int i = blockIdx.x * blockDim.x + threadIdx.x;
    if (i >= N) return;
    float dtf = 1.0f;
    if (dtp != nullptr) {
        int v = dtp[0];
        if (v >= 1 && v <= 1000000) dtf = (float)v;
        else { float f = __int_as_float(v); if (f > 0.0f && f < 1.0e6f) dtf = f; }
    }
    ts[i] = (float)i * dtf;
}

// ---------------------------------------------------------------------------
extern "C" void kernel_launch(void* const* d_in, const int* in_sizes, int n_in,
                              void* d_out, int out_size)
{
    const float* x0   = (const float*)d_in[0];
    const float* e0   = (const float*)d_in[1];
    const float* e1   = (const float*)d_in[2];
    const float* e2   = (const float*)d_in[3];
    const float* spd  = (const float*)d_in[4];
    const float* pan  = (const float*)d_in[5];
    const float* nan_ = (const float*)d_in[6];

    const int B = in_sizes[0] / 3;
    const int N = (int)((long long)in_sizes[4] / B);

    float* out    = (float*)d_out;
    float* ts     = out;
    float* X      = out + N;
    float* states = X + (size_t)3 * B * N;
    float* sp_o   = states + (size_t)B * N;
    float* pa_o   = sp_o   + (size_t)B * N;
    float* na_o   = pa_o   + (size_t)B * N;

    const int* dtp = (n_in > 8) ? (const int*)d_in[8] : nullptr;

    const size_t smem_bytes = (size_t)SMEM_FLOATS * sizeof(float);  // ~28 KB
    const bool fast = (N == 1024) && (B % 2 == 0);

    if (fast) {
        cudaFuncSetAttribute(fused_kernel,
                             cudaFuncAttributeMaxDynamicSharedMemorySize,
                             (int)smem_bytes);
        fused_kernel<<<B / 2, THREADS, smem_bytes>>>(
            x0, e0, e1, e2, spd, pan, nan_,
            ts, X, states, sp_o, pa_o, na_o, dtp, B, N);
    } else {
        const size_t bn_bytes = (size_t)B * N * sizeof(float);
        explorer_kernel<<<(B + PPB - 1) / PPB, PPB>>>(x0, e0, e1, e2,
                                                      spd, pan, nan_, X, B, N);
        ts_kernel<<<(N + 255) / 256, 256>>>(ts, N, dtp);
        cudaMemsetAsync(states, 0, bn_bytes, 0);
        cudaMemcpyAsync(sp_o, d_in[4], bn_bytes, cudaMemcpyDeviceToDevice, 0);
        cudaMemcpyAsync(pa_o, d_in[5], bn_bytes, cudaMemcpyDeviceToDevice, 0);
        cudaMemcpyAsync(na_o, d_in[6], bn_bytes, cudaMemcpyDeviceToDevice, 0);
    }

    (void)out_size; (void)n_in;
}

// round 13
// speedup vs baseline: 1.3747x; 1.0347x over previous
#include <cuda_runtime.h>
#include <cstdint>

// ---------------------------------------------------------------------------
// ParticleExplorer — fused time-parallel kernel, L=8 chunks, 4 warps/particle,
// f32x2-packed arithmetic (components 0,1 packed; component 2 scalar).
// Per step: E <- E * Rz(pa) * Ry(na);  x <- x + sp * E.col0
// N = 1024 = 128 chunks x 8 steps. Block = 8 warps = 2 particles.
// Output: ts[N] | X[B][N][3] | states[B][N]=0 | speeds | pa | na
// ---------------------------------------------------------------------------

#define LCH 8
#define NWARP 8
#define THREADS (NWARP * 32)

#define SIN_PITCH 36
#define SIN_W (LCH * SIN_PITCH)                       // 288 floats per array
#define GLUE_OFF (NWARP * (3 * SIN_W))                // 6912
#define SMEM_FLOATS (GLUE_OFF + 2 * 48)               // + glue (2 particles x 4x12)

typedef unsigned long long u64;

__device__ __forceinline__ u64 pk2(float lo, float hi) {
    u64 r; asm("mov.b64 %0,{%1,%2};" : "=l"(r) : "f"(lo), "f"(hi)); return r;
}
__device__ __forceinline__ void up2(u64 v, float& lo, float& hi) {
    asm("mov.b64 {%0,%1},%2;" : "=f"(lo), "=f"(hi) : "l"(v));
}
__device__ __forceinline__ u64 bc2(float s) { return pk2(s, s); }
__device__ __forceinline__ u64 fma2(u64 a, u64 b, u64 c) {
    u64 d; asm("fma.rn.f32x2 %0,%1,%2,%3;" : "=l"(d) : "l"(a), "l"(b), "l"(c)); return d;
}
__device__ __forceinline__ u64 mul2(u64 a, u64 b) {
    u64 d; asm("mul.rn.f32x2 %0,%1,%2;" : "=l"(d) : "l"(a), "l"(b)); return d;
}

// Affine element: columns e0,e1,e2 + displacement, components (0,1) packed.
struct Aff {
    u64 A, B, C, D;
    float a2, b2, c2, d2;
};

__device__ __forceinline__ Aff aff_identity() {
    Aff o;
    o.A = pk2(1.f, 0.f); o.a2 = 0.f;
    o.B = pk2(0.f, 1.f); o.b2 = 0.f;
    o.C = pk2(0.f, 0.f); o.c2 = 1.f;
    o.D = pk2(0.f, 0.f); o.d2 = 0.f;
    return o;
}

// compose: r earlier, q later (q's coeffs in r's start basis). Same nesting
// order as the scalar version -> bit-identical per-lane rounding.
__device__ __forceinline__ Aff compose_p(const Aff& r, const Aff& q) {
    Aff o; float q0, q1, q2;
    up2(q.A, q0, q1); q2 = q.a2;
    o.A  = fma2(bc2(q0), r.A, fma2(bc2(q1), r.B, mul2(bc2(q2), r.C)));
    o.a2 = fmaf(q0, r.a2, fmaf(q1, r.b2, q2 * r.c2));
    up2(q.B, q0, q1); q2 = q.b2;
    o.B  = fma2(bc2(q0), r.A, fma2(bc2(q1), r.B, mul2(bc2(q2), r.C)));
    o.b2 = fmaf(q0, r.a2, fmaf(q1, r.b2, q2 * r.c2));
    up2(q.C, q0, q1); q2 = q.c2;
    o.C  = fma2(bc2(q0), r.A, fma2(bc2(q1), r.B, mul2(bc2(q2), r.C)));
    o.c2 = fmaf(q0, r.a2, fmaf(q1, r.b2, q2 * r.c2));
    up2(q.D, q0, q1); q2 = q.d2;
    o.D  = fma2(bc2(q0), r.A, fma2(bc2(q1), r.B, fma2(bc2(q2), r.C, r.D)));
    o.d2 = fmaf(q0, r.a2, fmaf(q1, r.b2, fmaf(q2, r.c2, r.d2)));
    return o;
}

__device__ __forceinline__ Aff shfl_up_aff(const Aff& v, int off) {
    Aff o;
    o.A  = __shfl_up_sync(0xffffffffu, v.A,  off);
    o.B  = __shfl_up_sync(0xffffffffu, v.B,  off);
    o.C  = __shfl_up_sync(0xffffffffu, v.C,  off);
    o.D  = __shfl_up_sync(0xffffffffu, v.D,  off);
    o.a2 = __shfl_up_sync(0xffffffffu, v.a2, off);
    o.b2 = __shfl_up_sync(0xffffffffu, v.b2, off);
    o.c2 = __shfl_up_sync(0xffffffffu, v.c2, off);
    o.d2 = __shfl_up_sync(0xffffffffu, v.d2, off);
    return o;
}

// Packed step: E <- E * Rz(pa) * Ry(na). Same op order as scalar version.
__device__ __forceinline__ void frame_step_p(float pa, float na,
    u64& A, u64& B, u64& C, float& a2, float& b2, float& c2)
{
    float s1, cc1, s2, cc2;
    __sincosf(pa, &s1, &cc1);
    __sincosf(na, &s2, &cc2);
    float p00 = cc1 * cc2, p10 = s1 * cc2;
    float p02 = cc1 * s2,  p12 = s1 * s2;

    u64 nA = fma2(bc2(p00), A, fma2(bc2(p10), B, mul2(bc2(-s2), C)));
    float na2 = fmaf(p00, a2, fmaf(p10, b2, -s2 * c2));
    u64 nB = fma2(bc2(cc1), B, mul2(bc2(-s1), A));
    float nb2 = fmaf(cc1, b2, -s1 * a2);
    u64 nC = fma2(bc2(p02), A, fma2(bc2(p12), B, mul2(bc2(cc2), C)));
    float nc2 = fmaf(p02, a2, fmaf(p12, b2, cc2 * c2));
    A = nA; B = nB; C = nC; a2 = na2; b2 = nb2; c2 = nc2;
}

// Scalar frame step (fallback kernel only).
__device__ __forceinline__ void frame_step(float pa, float na,
    float& a0, float& a1, float& a2,
    float& b0, float& b1, float& b2,
    float& c0, float& c1, float& c2)
{
    float s1, cc1, s2, cc2;
    __sincosf(pa, &s1, &cc1);
    __sincosf(na, &s2, &cc2);
    float p00 = cc1 * cc2, p10 = s1 * cc2;
    float p02 = cc1 * s2,  p12 = s1 * s2;

    float na0 = fmaf(p00, a0, fmaf(p10, b0, -s2 * c0));
    float na1 = fmaf(p00, a1, fmaf(p10, b1, -s2 * c1));
    float na2 = fmaf(p00, a2, fmaf(p10, b2, -s2 * c2));
    float nb0 = fmaf(cc1, b0, -s1 * a0);
    float nb1 = fmaf(cc1, b1, -s1 * a1);
    float nb2 = fmaf(cc1, b2, -s1 * a2);
    float nc0 = fmaf(p02, a0, fmaf(p12, b0, cc2 * c0));
    float nc1 = fmaf(p02, a1, fmaf(p12, b1, cc2 * c1));
    float nc2 = fmaf(p02, a2, fmaf(p12, b2, cc2 * c2));
    a0 = na0; a1 = na1; a2 = na2;
    b0 = nb0; b1 = nb1; b2 = nb2;
    c0 = nc0; c1 = nc1; c2 = nc2;
}

__global__ void __launch_bounds__(THREADS, 5)
fused_kernel(const float* __restrict__ x0, const float* __restrict__ e0i,
             const float* __restrict__ e1i, const float* __restrict__ e2i,
             const float* __restrict__ spd, const float* __restrict__ pan,
             const float* __restrict__ nanp,
             float* __restrict__ ts, float* __restrict__ X,
             float* __restrict__ states, float* __restrict__ spo,
             float* __restrict__ pao, float* __restrict__ nao,
             const int* __restrict__ dtp, int B, int N)
{
    extern __shared__ float sm[];

    const int tid  = threadIdx.x;
    const int lane = tid & 31;
    const int w    = tid >> 5;
    const int q    = w & 3;                 // quarter of the timeline
    const int ps   = w >> 2;                // particle slot in block (0..1)
    const int p    = blockIdx.x * 2 + ps;
    const int gtid = blockIdx.x * THREADS + tid;

    if (gtid < N) {
        float dtf = 1.0f;
        if (dtp) {
            int vdt = dtp[0];
            if (vdt >= 1 && vdt <= 1000000) dtf = (float)vdt;
            else { float f = __int_as_float(vdt); if (f > 0.f && f < 1.0e6f) dtf = f; }
        }
        ts[gtid] = (float)gtid * dtf;
    }
    // No early return: __syncthreads below needs all threads (grid == B/2 exact).

    float* s_sp = sm + w * (3 * SIN_W);
    float* s_pa = s_sp + SIN_W;
    float* s_na = s_sp + 2 * SIN_W;
    float* glue = sm + GLUE_OFF + ps * 48;   // 4 totals x 12 floats

    const size_t pb = (size_t)p * N + (size_t)q * 256;
    const float4* g_sp = (const float4*)(spd  + pb);
    const float4* g_pa = (const float4*)(pan  + pb);
    const float4* g_na = (const float4*)(nanp + pb);
    float4* o_sp = (float4*)(spo    + pb);
    float4* o_pa = (float4*)(pao    + pb);
    float4* o_na = (float4*)(nao    + pb);
    float4* o_st = (float4*)(states + pb);
    const float4 zero4 = make_float4(0.f, 0.f, 0.f, 0.f);

    // ---- Stage: coalesced loads -> smem [step i][chunk c], pitch 36.
    #pragma unroll
    for (int j = 0; j < 2; j++) {
        int f = j * 32 + lane;
        float4 vs = g_sp[f], vp = g_pa[f], vn = g_na[f];
        o_sp[f] = vs; o_pa[f] = vp; o_na[f] = vn; o_st[f] = zero4;
        int c  = 16 * j + (lane >> 1);
        int i0 = (lane & 1) << 2;
        s_sp[(i0+0)*SIN_PITCH + c] = vs.x; s_sp[(i0+1)*SIN_PITCH + c] = vs.y;
        s_sp[(i0+2)*SIN_PITCH + c] = vs.z; s_sp[(i0+3)*SIN_PITCH + c] = vs.w;
        s_pa[(i0+0)*SIN_PITCH + c] = vp.x; s_pa[(i0+1)*SIN_PITCH + c] = vp.y;
        s_pa[(i0+2)*SIN_PITCH + c] = vp.z; s_pa[(i0+3)*SIN_PITCH + c] = vp.w;
        s_na[(i0+0)*SIN_PITCH + c] = vn.x; s_na[(i0+1)*SIN_PITCH + c] = vn.y;
        s_na[(i0+2)*SIN_PITCH + c] = vn.z; s_na[(i0+3)*SIN_PITCH + c] = vn.w;
    }
    __syncwarp();

    // ---- Pass 1: 8-step packed chunk transform; d_i overwrites inputs ----------
    u64 A = pk2(1.f, 0.f), Bv = pk2(0.f, 1.f), C = pk2(0.f, 0.f);
    float a2 = 0.f, b2 = 0.f, c2 = 1.f;
    u64 D = pk2(0.f, 0.f);
    float d2 = 0.f;
    #pragma unroll
    for (int i = 0; i < LCH; i++) {
        float pa = s_pa[i*SIN_PITCH + lane];
        float na = s_na[i*SIN_PITCH + lane];
        float sp = s_sp[i*SIN_PITCH + lane];
        frame_step_p(pa, na, A, Bv, C, a2, b2, c2);
        D  = fma2(bc2(sp), A, D);
        d2 = fmaf(sp, a2, d2);
        float dd0, dd1; up2(D, dd0, dd1);
        s_sp[i*SIN_PITCH + lane] = dd0;
        s_pa[i*SIN_PITCH + lane] = dd1;
        s_na[i*SIN_PITCH + lane] = d2;
    }

    Aff v; v.A = A; v.B = Bv; v.C = C; v.D = D;
    v.a2 = a2; v.b2 = b2; v.c2 = c2; v.d2 = d2;

    // ---- Intra-warp inclusive scan (packed affine composition) ----------------
    #pragma unroll
    for (int off = 1; off <= 16; off <<= 1) {
        Aff o = shfl_up_aff(v, off);
        if (lane >= off) v = compose_p(o, v);
    }

    // Publish each quarter's total (lane 31 inclusive) as 12 floats.
    if (lane == 31) {
        float t0, t1;
        up2(v.A, t0, t1); glue[q*12+0] = t0; glue[q*12+1] = t1; glue[q*12+2]  = v.a2;
        up2(v.B, t0, t1); glue[q*12+3] = t0; glue[q*12+4] = t1; glue[q*12+5]  = v.b2;
        up2(v.C, t0, t1); glue[q*12+6] = t0; glue[q*12+7] = t1; glue[q*12+8]  = v.c2;
        up2(v.D, t0, t1); glue[q*12+9] = t0; glue[q*12+10] = t1; glue[q*12+11] = v.d2;
    }
    __syncthreads();

    // Exclusive prefix within warp.
    Aff e = shfl_up_aff(v, 1);
    if (lane == 0) e = aff_identity();

    // Prepend earlier quarters' totals.
    if (q > 0) {
        Aff P;
        P.A = pk2(glue[0], glue[1]);  P.a2 = glue[2];
        P.B = pk2(glue[3], glue[4]);  P.b2 = glue[5];
        P.C = pk2(glue[6], glue[7]);  P.c2 = glue[8];
        P.D = pk2(glue[9], glue[10]); P.d2 = glue[11];
        for (int k = 1; k < q; k++) {
            Aff T;
            T.A = pk2(glue[k*12+0], glue[k*12+1]);  T.a2 = glue[k*12+2];
            T.B = pk2(glue[k*12+3], glue[k*12+4]);  T.b2 = glue[k*12+5];
            T.C = pk2(glue[k*12+6], glue[k*12+7]);  T.c2 = glue[k*12+8];
            T.D = pk2(glue[k*12+9], glue[k*12+10]); T.d2 = glue[k*12+11];
            P = compose_p(P, T);
        }
        e = compose_p(P, e);
    }

    // ---- Glue with particle initial frame/pos: one packed compose --------------
    Aff r0;
    r0.A = pk2(e0i[p*3+0], e0i[p*3+1]); r0.a2 = e0i[p*3+2];
    r0.B = pk2(e1i[p*3+0], e1i[p*3+1]); r0.b2 = e1i[p*3+2];
    r0.C = pk2(e2i[p*3+0], e2i[p*3+1]); r0.c2 = e2i[p*3+2];
    r0.D = pk2(x0 [p*3+0], x0 [p*3+1]); r0.d2 = x0 [p*3+2];
    Aff s = compose_p(r0, e);

    // Gram-Schmidt renorm (scalar; once per thread).
    float a0, a1, b0, b1, c0, c1, x, y, z;
    up2(s.A, a0, a1); a2 = s.a2;
    up2(s.B, b0, b1); b2 = s.b2;
    up2(s.D, x, y);   z  = s.d2;
    {
        float inv = rsqrtf(fmaf(a0,a0, fmaf(a1,a1, a2*a2)));
        a0*=inv; a1*=inv; a2*=inv;
        float dd = fmaf(b0,a0, fmaf(b1,a1, b2*a2));
        b0 = fmaf(-dd,a0,b0); b1 = fmaf(-dd,a1,b1); b2 = fmaf(-dd,a2,b2);
        inv = rsqrtf(fmaf(b0,b0, fmaf(b1,b1, b2*b2)));
        b0*=inv; b1*=inv; b2*=inv;
        c0 = a1*b2 - a2*b1;
        c1 = a2*b0 - a0*b2;
        c2 = a0*b1 - a1*b0;
    }
    A  = pk2(a0, a1);
    Bv = pk2(b0, b1);
    C  = pk2(c0, c1);
    u64 X01 = pk2(x, y);

    // ---- Pass 2: x_i = x_start + d_i . E_start (packed matvec), in place -------
    #pragma unroll
    for (int i = 0; i < LCH; i++) {
        float dd0 = s_sp[i*SIN_PITCH + lane];
        float dd1 = s_pa[i*SIN_PITCH + lane];
        float dd2 = s_na[i*SIN_PITCH + lane];
        u64 o01 = fma2(bc2(dd0), A, fma2(bc2(dd1), Bv, fma2(bc2(dd2), C, X01)));
        float oz = fmaf(dd0, a2, fmaf(dd1, b2, fmaf(dd2, c2, z)));
        float ox, oy; up2(o01, ox, oy);
        s_sp[i*SIN_PITCH + lane] = ox;
        s_pa[i*SIN_PITCH + lane] = oy;
        s_na[i*SIN_PITCH + lane] = oz;
    }
    __syncwarp();

    // ---- Flush X: 192 float4 per warp-quarter, x3-periodic addressing. ---------
    float4* gX = (float4*)(X + (size_t)p * 3 * N + (size_t)q * 768);
    #pragma unroll
    for (int jc = 0; jc < 3; jc++) {
        const float* arr[4];
        int addr[4];
        #pragma unroll
        for (int k = 0; k < 4; k++) {
            int ek   = 128 * jc + 4 * lane + k;
            int own  = ek / 24;
            int rem  = ek - own * 24;
            int i    = rem / 3;
            int comp = rem - i * 3;
            arr[k]  = (comp == 0) ? s_sp : (comp == 1) ? s_pa : s_na;
            addr[k] = i * SIN_PITCH + own;
        }
        #pragma unroll
        for (int m = 0; m < 2; m++) {
            int j = jc + 3 * m;
            float4 r;
            r.x = arr[0][addr[0] + 16 * m];
            r.y = arr[1][addr[1] + 16 * m];
            r.z = arr[2][addr[2] + 16 * m];
            r.w = arr[3][addr[3] + 16 * m];
            gX[j * 32 + lane] = r;
        }
    }
}

// ---------------------------------------------------------------------------
// Fallback (proven round-2 path) for unexpected shapes.
// ---------------------------------------------------------------------------
#define PPB 32
#define TT  32
#define SPITCH 33

__global__ void __launch_bounds__(PPB)
explorer_kernel(const float* __restrict__ x0, const float* __restrict__ e0i,
                const float* __restrict__ e1i, const float* __restrict__ e2i,
                const float* __restrict__ spd, const float* __restrict__ pan,
                const float* __restrict__ nan_, float* __restrict__ X,
                int B, int N)
{
    __shared__ float s_sp[TT][SPITCH];
    __shared__ float s_pa[TT][SPITCH];
    __shared__ float s_na[TT][SPITCH];
    __shared__ float s_X[3 * TT][SPITCH];

    const int lane  = threadIdx.x;
    const int pbase = blockIdx.x * PPB;
    const int p     = pbase + lane;
    const bool act  = (p < B);

    float a0=1.f,a1=0.f,a2=0.f, b0=0.f,b1=1.f,b2=0.f, c0=0.f,c1=0.f,c2=1.f;
    float x=0.f, y=0.f, z=0.f;
    if (act) {
        a0=e0i[p*3+0]; a1=e0i[p*3+1]; a2=e0i[p*3+2];
        b0=e1i[p*3+0]; b1=e1i[p*3+1]; b2=e1i[p*3+2];
        c0=e2i[p*3+0]; c1=e2i[p*3+1]; c2=e2i[p*3+2];
        x =x0 [p*3+0]; y =x0 [p*3+1]; z =x0 [p*3+2];
    }

    for (int t0 = 0; t0 < N; t0 += TT) {
        #pragma unroll
        for (int k = 0; k < PPB; k++) {
            int gp = pbase + k;
            float vs=0.f, vp=0.f, vn=0.f;
            if (gp < B && t0 + lane < N) {
                size_t gidx = (size_t)gp * N + (size_t)t0 + lane;
                vs = spd[gidx]; vp = pan[gidx]; vn = nan_[gidx];
            }
            s_sp[lane][k]=vs; s_pa[lane][k]=vp; s_na[lane][k]=vn;
        }
        __syncthreads();

        if (act) {
            int nt = (N - t0 < TT) ? (N - t0) : TT;
            for (int tt = 0; tt < nt; tt++) {
                frame_step(s_pa[tt][lane], s_na[tt][lane],
                           a0,a1,a2,b0,b1,b2,c0,c1,c2);
                float sv = s_sp[tt][lane];
                x = fmaf(sv,a0,x); y = fmaf(sv,a1,y); z = fmaf(sv,a2,z);
                s_X[3*tt+0][lane]=x; s_X[3*tt+1][lane]=y; s_X[3*tt+2][lane]=z;
            }
            float inv = rsqrtf(fmaf(a0,a0, fmaf(a1,a1, a2*a2)));
            a0*=inv; a1*=inv; a2*=inv;
            float d = fmaf(b0,a0, fmaf(b1,a1, b2*a2));
            b0=fmaf(-d,a0,b0); b1=fmaf(-d,a1,b1); b2=fmaf(-d,a2,b2);
            inv = rsqrtf(fmaf(b0,b0, fmaf(b1,b1, b2*b2)));
            b0*=inv; b1*=inv; b2*=inv;
            c0=a1*b2-a2*b1; c1=a2*b0-a0*b2; c2=a0*b1-a1*b0;
        }
        __syncthreads();

        #pragma unroll
        for (int k = 0; k < PPB; k++) {
            int gp = pbase + k;
            if (gp < B) {
                size_t bidx = (size_t)gp*3*N + (size_t)t0*3;
                #pragma unroll
                for (int chn = 0; chn < 3; chn++)
                    if (t0*3 + chn*32 + lane < 3*N)
                        X[bidx + chn*32 + lane] = s_X[chn*32 + lane][k];
            }
        }
    }
}

__global__ void ts_kernel(float* __restrict__ ts, int N, const int* __restrict__ dtp)
{
    int i = blockIdx.x * blockDim.x + threadIdx.x;
    if (i >= N) return;
    float dtf = 1.0f;
    if (dtp != nullptr) {
        int v = dtp[0];
        if (v >= 1 && v <= 1000000) dtf = (float)v;
        else { float f = __int_as_float(v); if (f > 0.0f && f < 1.0e6f) dtf = f; }
    }
    ts[i] = (float)i * dtf;
}

// ---------------------------------------------------------------------------
extern "C" void kernel_launch(void* const* d_in, const int* in_sizes, int n_in,
                              void* d_out, int out_size)
{
    const float* x0   = (const float*)d_in[0];
    const float* e0   = (const float*)d_in[1];
    const float* e1   = (const float*)d_in[2];
    const float* e2   = (const float*)d_in[3];
    const float* spd  = (const float*)d_in[4];
    const float* pan  = (const float*)d_in[5];
    const float* nan_ = (const float*)d_in[6];

    const int B = in_sizes[0] / 3;
    const int N = (int)((long long)in_sizes[4] / B);

    float* out    = (float*)d_out;
    float* ts     = out;
    float* X      = out + N;
    float* states = X + (size_t)3 * B * N;
    float* sp_o   = states + (size_t)B * N;
    float* pa_o   = sp_o   + (size_t)B * N;
    float* na_o   = pa_o   + (size_t)B * N;

    const int* dtp = (n_in > 8) ? (const int*)d_in[8] : nullptr;

    const size_t smem_bytes = (size_t)SMEM_FLOATS * sizeof(float);  // ~28 KB
    const bool fast = (N == 1024) && (B % 2 == 0);

    if (fast) {
        cudaFuncSetAttribute(fused_kernel,
                             cudaFuncAttributeMaxDynamicSharedMemorySize,
                             (int)smem_bytes);
        fused_kernel<<<B / 2, THREADS, smem_bytes>>>(
            x0, e0, e1, e2, spd, pan, nan_,
            ts, X, states, sp_o, pa_o, na_o, dtp, B, N);
    } else {
        const size_t bn_bytes = (size_t)B * N * sizeof(float);
        explorer_kernel<<<(B + PPB - 1) / PPB, PPB>>>(x0, e0, e1, e2,
                                                      spd, pan, nan_, X, B, N);
        ts_kernel<<<(N + 255) / 256, 256>>>(ts, N, dtp);
        cudaMemsetAsync(states, 0, bn_bytes, 0);
        cudaMemcpyAsync(sp_o, d_in[4], bn_bytes, cudaMemcpyDeviceToDevice, 0);
        cudaMemcpyAsync(pa_o, d_in[5], bn_bytes, cudaMemcpyDeviceToDevice, 0);
        cudaMemcpyAsync(na_o, d_in[6], bn_bytes, cudaMemcpyDeviceToDevice, 0);
    }

    (void)out_size; (void)n_in;
}

// round 14
// speedup vs baseline: 1.3835x; 1.0065x over previous
#include <cuda_runtime.h>
#include <cstdint>

// ---------------------------------------------------------------------------
// ParticleExplorer — fused time-parallel kernel, L=8 chunks, 4 warps/particle,
// f32x2-packed arithmetic, streaming (ld.cs/st.cs) global accesses,
// 1 particle per 128-thread block (10 blocks/SM).
// Per step: E <- E * Rz(pa) * Ry(na);  x <- x + sp * E.col0
// N = 1024 = 128 chunks x 8 steps.
// Output: ts[N] | X[B][N][3] | states[B][N]=0 | speeds | pa | na
// ---------------------------------------------------------------------------

#define LCH 8
#define NWARP 4
#define THREADS (NWARP * 32)

#define SIN_PITCH 36
#define SIN_W (LCH * SIN_PITCH)                       // 288 floats per array
#define GLUE_OFF (NWARP * (3 * SIN_W))                // 3456
#define SMEM_FLOATS (GLUE_OFF + 48)                   // + glue (4 x 12)

typedef unsigned long long u64;

__device__ __forceinline__ u64 pk2(float lo, float hi) {
    u64 r; asm("mov.b64 %0,{%1,%2};" : "=l"(r) : "f"(lo), "f"(hi)); return r;
}
__device__ __forceinline__ void up2(u64 v, float& lo, float& hi) {
    asm("mov.b64 {%0,%1},%2;" : "=f"(lo), "=f"(hi) : "l"(v));
}
__device__ __forceinline__ u64 bc2(float s) { return pk2(s, s); }
__device__ __forceinline__ u64 fma2(u64 a, u64 b, u64 c) {
    u64 d; asm("fma.rn.f32x2 %0,%1,%2,%3;" : "=l"(d) : "l"(a), "l"(b), "l"(c)); return d;
}
__device__ __forceinline__ u64 mul2(u64 a, u64 b) {
    u64 d; asm("mul.rn.f32x2 %0,%1,%2;" : "=l"(d) : "l"(a), "l"(b)); return d;
}

// Affine element: columns e0,e1,e2 + displacement, components (0,1) packed.
struct Aff {
    u64 A, B, C, D;
    float a2, b2, c2, d2;
};

__device__ __forceinline__ Aff aff_identity() {
    Aff o;
    o.A = pk2(1.f, 0.f); o.a2 = 0.f;
    o.B = pk2(0.f, 1.f); o.b2 = 0.f;
    o.C = pk2(0.f, 0.f); o.c2 = 1.f;
    o.D = pk2(0.f, 0.f); o.d2 = 0.f;
    return o;
}

// compose: r earlier, q later (q's coeffs in r's start basis).
__device__ __forceinline__ Aff compose_p(const Aff& r, const Aff& q) {
    Aff o; float q0, q1, q2;
    up2(q.A, q0, q1); q2 = q.a2;
    o.A  = fma2(bc2(q0), r.A, fma2(bc2(q1), r.B, mul2(bc2(q2), r.C)));
    o.a2 = fmaf(q0, r.a2, fmaf(q1, r.b2, q2 * r.c2));
    up2(q.B, q0, q1); q2 = q.b2;
    o.B  = fma2(bc2(q0), r.A, fma2(bc2(q1), r.B, mul2(bc2(q2), r.C)));
    o.b2 = fmaf(q0, r.a2, fmaf(q1, r.b2, q2 * r.c2));
    up2(q.C, q0, q1); q2 = q.c2;
    o.C  = fma2(bc2(q0), r.A, fma2(bc2(q1), r.B, mul2(bc2(q2), r.C)));
    o.c2 = fmaf(q0, r.a2, fmaf(q1, r.b2, q2 * r.c2));
    up2(q.D, q0, q1); q2 = q.d2;
    o.D  = fma2(bc2(q0), r.A, fma2(bc2(q1), r.B, fma2(bc2(q2), r.C, r.D)));
    o.d2 = fmaf(q0, r.a2, fmaf(q1, r.b2, fmaf(q2, r.c2, r.d2)));
    return o;
}

__device__ __forceinline__ Aff shfl_up_aff(const Aff& v, int off) {
    Aff o;
    o.A  = __shfl_up_sync(0xffffffffu, v.A,  off);
    o.B  = __shfl_up_sync(0xffffffffu, v.B,  off);
    o.C  = __shfl_up_sync(0xffffffffu, v.C,  off);
    o.D  = __shfl_up_sync(0xffffffffu, v.D,  off);
    o.a2 = __shfl_up_sync(0xffffffffu, v.a2, off);
    o.b2 = __shfl_up_sync(0xffffffffu, v.b2, off);
    o.c2 = __shfl_up_sync(0xffffffffu, v.c2, off);
    o.d2 = __shfl_up_sync(0xffffffffu, v.d2, off);
    return o;
}

// Packed step: E <- E * Rz(pa) * Ry(na).
__device__ __forceinline__ void frame_step_p(float pa, float na,
    u64& A, u64& B, u64& C, float& a2, float& b2, float& c2)
{
    float s1, cc1, s2, cc2;
    __sincosf(pa, &s1, &cc1);
    __sincosf(na, &s2, &cc2);
    float p00 = cc1 * cc2, p10 = s1 * cc2;
    float p02 = cc1 * s2,  p12 = s1 * s2;

    u64 nA = fma2(bc2(p00), A, fma2(bc2(p10), B, mul2(bc2(-s2), C)));
    float na2 = fmaf(p00, a2, fmaf(p10, b2, -s2 * c2));
    u64 nB = fma2(bc2(cc1), B, mul2(bc2(-s1), A));
    float nb2 = fmaf(cc1, b2, -s1 * a2);
    u64 nC = fma2(bc2(p02), A, fma2(bc2(p12), B, mul2(bc2(cc2), C)));
    float nc2 = fmaf(p02, a2, fmaf(p12, b2, cc2 * c2));
    A = nA; B = nB; C = nC; a2 = na2; b2 = nb2; c2 = nc2;
}

// Scalar frame step (fallback kernel only).
__device__ __forceinline__ void frame_step(float pa, float na,
    float& a0, float& a1, float& a2,
    float& b0, float& b1, float& b2,
    float& c0, float& c1, float& c2)
{
    float s1, cc1, s2, cc2;
    __sincosf(pa, &s1, &cc1);
    __sincosf(na, &s2, &cc2);
    float p00 = cc1 * cc2, p10 = s1 * cc2;
    float p02 = cc1 * s2,  p12 = s1 * s2;

    float na0 = fmaf(p00, a0, fmaf(p10, b0, -s2 * c0));
    float na1 = fmaf(p00, a1, fmaf(p10, b1, -s2 * c1));
    float na2 = fmaf(p00, a2, fmaf(p10, b2, -s2 * c2));
    float nb0 = fmaf(cc1, b0, -s1 * a0);
    float nb1 = fmaf(cc1, b1, -s1 * a1);
    float nb2 = fmaf(cc1, b2, -s1 * a2);
    float nc0 = fmaf(p02, a0, fmaf(p12, b0, cc2 * c0));
    float nc1 = fmaf(p02, a1, fmaf(p12, b1, cc2 * c1));
    float nc2 = fmaf(p02, a2, fmaf(p12, b2, cc2 * c2));
    a0 = na0; a1 = na1; a2 = na2;
    b0 = nb0; b1 = nb1; b2 = nb2;
    c0 = nc0; c1 = nc1; c2 = nc2;
}

__global__ void __launch_bounds__(THREADS, 10)
fused_kernel(const float* __restrict__ x0, const float* __restrict__ e0i,
             const float* __restrict__ e1i, const float* __restrict__ e2i,
             const float* __restrict__ spd, const float* __restrict__ pan,
             const float* __restrict__ nanp,
             float* __restrict__ ts, float* __restrict__ X,
             float* __restrict__ states, float* __restrict__ spo,
             float* __restrict__ pao, float* __restrict__ nao,
             const int* __restrict__ dtp, int B, int N)
{
    extern __shared__ float sm[];

    const int tid  = threadIdx.x;
    const int lane = tid & 31;
    const int q    = tid >> 5;              // quarter of the timeline (warp id)
    const int p    = blockIdx.x;            // one particle per block
    const int gtid = blockIdx.x * THREADS + tid;

    if (gtid < N) {
        float dtf = 1.0f;
        if (dtp) {
            int vdt = dtp[0];
            if (vdt >= 1 && vdt <= 1000000) dtf = (float)vdt;
            else { float f = __int_as_float(vdt); if (f > 0.f && f < 1.0e6f) dtf = f; }
        }
        ts[gtid] = (float)gtid * dtf;
    }

    float* s_sp = sm + q * (3 * SIN_W);
    float* s_pa = s_sp + SIN_W;
    float* s_na = s_sp + 2 * SIN_W;
    float* glue = sm + GLUE_OFF;             // 4 totals x 12 floats

    const size_t pb = (size_t)p * N + (size_t)q * 256;
    const float4* g_sp = (const float4*)(spd  + pb);
    const float4* g_pa = (const float4*)(pan  + pb);
    const float4* g_na = (const float4*)(nanp + pb);
    float4* o_sp = (float4*)(spo    + pb);
    float4* o_pa = (float4*)(pao    + pb);
    float4* o_na = (float4*)(nao    + pb);
    float4* o_st = (float4*)(states + pb);
    const float4 zero4 = make_float4(0.f, 0.f, 0.f, 0.f);

    // ---- Stage: streaming loads -> smem [step i][chunk c], pitch 36;
    //      aux outputs written with streaming stores (read-once/write-once).
    #pragma unroll
    for (int j = 0; j < 2; j++) {
        int f = j * 32 + lane;
        float4 vs = __ldcs(&g_sp[f]);
        float4 vp = __ldcs(&g_pa[f]);
        float4 vn = __ldcs(&g_na[f]);
        __stcs(&o_sp[f], vs); __stcs(&o_pa[f], vp);
        __stcs(&o_na[f], vn); __stcs(&o_st[f], zero4);
        int c  = 16 * j + (lane >> 1);
        int i0 = (lane & 1) << 2;
        s_sp[(i0+0)*SIN_PITCH + c] = vs.x; s_sp[(i0+1)*SIN_PITCH + c] = vs.y;
        s_sp[(i0+2)*SIN_PITCH + c] = vs.z; s_sp[(i0+3)*SIN_PITCH + c] = vs.w;
        s_pa[(i0+0)*SIN_PITCH + c] = vp.x; s_pa[(i0+1)*SIN_PITCH + c] = vp.y;
        s_pa[(i0+2)*SIN_PITCH + c] = vp.z; s_pa[(i0+3)*SIN_PITCH + c] = vp.w;
        s_na[(i0+0)*SIN_PITCH + c] = vn.x; s_na[(i0+1)*SIN_PITCH + c] = vn.y;
        s_na[(i0+2)*SIN_PITCH + c] = vn.z; s_na[(i0+3)*SIN_PITCH + c] = vn.w;
    }
    __syncwarp();

    // ---- Pass 1: 8-step packed chunk transform; d_i overwrites inputs ----------
    u64 A = pk2(1.f, 0.f), Bv = pk2(0.f, 1.f), C = pk2(0.f, 0.f);
    float a2 = 0.f, b2 = 0.f, c2 = 1.f;
    u64 D = pk2(0.f, 0.f);
    float d2 = 0.f;
    #pragma unroll
    for (int i = 0; i < LCH; i++) {
        float pa = s_pa[i*SIN_PITCH + lane];
        float na = s_na[i*SIN_PITCH + lane];
        float sp = s_sp[i*SIN_PITCH + lane];
        frame_step_p(pa, na, A, Bv, C, a2, b2, c2);
        D  = fma2(bc2(sp), A, D);
        d2 = fmaf(sp, a2, d2);
        float dd0, dd1; up2(D, dd0, dd1);
        s_sp[i*SIN_PITCH + lane] = dd0;
        s_pa[i*SIN_PITCH + lane] = dd1;
        s_na[i*SIN_PITCH + lane] = d2;
    }

    Aff v; v.A = A; v.B = Bv; v.C = C; v.D = D;
    v.a2 = a2; v.b2 = b2; v.c2 = c2; v.d2 = d2;

    // ---- Intra-warp inclusive scan (packed affine composition) ----------------
    #pragma unroll
    for (int off = 1; off <= 16; off <<= 1) {
        Aff o = shfl_up_aff(v, off);
        if (lane >= off) v = compose_p(o, v);
    }

    // Publish each quarter's total (lane 31 inclusive) as 12 floats.
    if (lane == 31) {
        float t0, t1;
        up2(v.A, t0, t1); glue[q*12+0] = t0; glue[q*12+1] = t1; glue[q*12+2]  = v.a2;
        up2(v.B, t0, t1); glue[q*12+3] = t0; glue[q*12+4] = t1; glue[q*12+5]  = v.b2;
        up2(v.C, t0, t1); glue[q*12+6] = t0; glue[q*12+7] = t1; glue[q*12+8]  = v.c2;
        up2(v.D, t0, t1); glue[q*12+9] = t0; glue[q*12+10] = t1; glue[q*12+11] = v.d2;
    }
    __syncthreads();

    // Exclusive prefix within warp.
    Aff e = shfl_up_aff(v, 1);
    if (lane == 0) e = aff_identity();

    // Prepend earlier quarters' totals.
    if (q > 0) {
        Aff P;
        P.A = pk2(glue[0], glue[1]);  P.a2 = glue[2];
        P.B = pk2(glue[3], glue[4]);  P.b2 = glue[5];
        P.C = pk2(glue[6], glue[7]);  P.c2 = glue[8];
        P.D = pk2(glue[9], glue[10]); P.d2 = glue[11];
        for (int k = 1; k < q; k++) {
            Aff T;
            T.A = pk2(glue[k*12+0], glue[k*12+1]);  T.a2 = glue[k*12+2];
            T.B = pk2(glue[k*12+3], glue[k*12+4]);  T.b2 = glue[k*12+5];
            T.C = pk2(glue[k*12+6], glue[k*12+7]);  T.c2 = glue[k*12+8];
            T.D = pk2(glue[k*12+9], glue[k*12+10]); T.d2 = glue[k*12+11];
            P = compose_p(P, T);
        }
        e = compose_p(P, e);
    }

    // ---- Glue with particle initial frame/pos: one packed compose --------------
    Aff r0;
    r0.A = pk2(e0i[p*3+0], e0i[p*3+1]); r0.a2 = e0i[p*3+2];
    r0.B = pk2(e1i[p*3+0], e1i[p*3+1]); r0.b2 = e1i[p*3+2];
    r0.C = pk2(e2i[p*3+0], e2i[p*3+1]); r0.c2 = e2i[p*3+2];
    r0.D = pk2(x0 [p*3+0], x0 [p*3+1]); r0.d2 = x0 [p*3+2];
    Aff s = compose_p(r0, e);

    // Gram-Schmidt renorm (scalar; once per thread).
    float a0, a1, b0, b1, c0, c1, x, y, z;
    up2(s.A, a0, a1); a2 = s.a2;
    up2(s.B, b0, b1); b2 = s.b2;
    up2(s.D, x, y);   z  = s.d2;
    {
        float inv = rsqrtf(fmaf(a0,a0, fmaf(a1,a1, a2*a2)));
        a0*=inv; a1*=inv; a2*=inv;
        float dd = fmaf(b0,a0, fmaf(b1,a1, b2*a2));
        b0 = fmaf(-dd,a0,b0); b1 = fmaf(-dd,a1,b1); b2 = fmaf(-dd,a2,b2);
        inv = rsqrtf(fmaf(b0,b0, fmaf(b1,b1, b2*b2)));
        b0*=inv; b1*=inv; b2*=inv;
        c0 = a1*b2 - a2*b1;
        c1 = a2*b0 - a0*b2;
        c2 = a0*b1 - a1*b0;
    }
    A  = pk2(a0, a1);
    Bv = pk2(b0, b1);
    C  = pk2(c0, c1);
    u64 X01 = pk2(x, y);

    // ---- Pass 2: x_i = x_start + d_i . E_start (packed matvec), in place -------
    #pragma unroll
    for (int i = 0; i < LCH; i++) {
        float dd0 = s_sp[i*SIN_PITCH + lane];
        float dd1 = s_pa[i*SIN_PITCH + lane];
        float dd2 = s_na[i*SIN_PITCH + lane];
        u64 o01 = fma2(bc2(dd0), A, fma2(bc2(dd1), Bv, fma2(bc2(dd2), C, X01)));
        float oz = fmaf(dd0, a2, fmaf(dd1, b2, fmaf(dd2, c2, z)));
        float ox, oy; up2(o01, ox, oy);
        s_sp[i*SIN_PITCH + lane] = ox;
        s_pa[i*SIN_PITCH + lane] = oy;
        s_na[i*SIN_PITCH + lane] = oz;
    }
    __syncwarp();

    // ---- Flush X: 192 float4 per warp-quarter, x3-periodic addressing,
    //      streaming stores.
    float4* gX = (float4*)(X + (size_t)p * 3 * N + (size_t)q * 768);
    #pragma unroll
    for (int jc = 0; jc < 3; jc++) {
        const float* arr[4];
        int addr[4];
        #pragma unroll
        for (int k = 0; k < 4; k++) {
            int ek   = 128 * jc + 4 * lane + k;
            int own  = ek / 24;
            int rem  = ek - own * 24;
            int i    = rem / 3;
            int comp = rem - i * 3;
            arr[k]  = (comp == 0) ? s_sp : (comp == 1) ? s_pa : s_na;
            addr[k] = i * SIN_PITCH + own;
        }
        #pragma unroll
        for (int m = 0; m < 2; m++) {
            int j = jc + 3 * m;
            float4 r;
            r.x = arr[0][addr[0] + 16 * m];
            r.y = arr[1][addr[1] + 16 * m];
            r.z = arr[2][addr[2] + 16 * m];
            r.w = arr[3][addr[3] + 16 * m];
            __stcs(&gX[j * 32 + lane], r);
        }
    }
}

// ---------------------------------------------------------------------------
// Fallback (proven round-2 path) for unexpected shapes.
// ---------------------------------------------------------------------------
#define PPB 32
#define TT  32
#define SPITCH 33

__global__ void __launch_bounds__(PPB)
explorer_kernel(const float* __restrict__ x0, const float* __restrict__ e0i,
                const float* __restrict__ e1i, const float* __restrict__ e2i,
                const float* __restrict__ spd, const float* __restrict__ pan,
                const float* __restrict__ nan_, float* __restrict__ X,
                int B, int N)
{
    __shared__ float s_sp[TT][SPITCH];
    __shared__ float s_pa[TT][SPITCH];
    __shared__ float s_na[TT][SPITCH];
    __shared__ float s_X[3 * TT][SPITCH];

    const int lane  = threadIdx.x;
    const int pbase = blockIdx.x * PPB;
    const int p     = pbase + lane;
    const bool act  = (p < B);

    float a0=1.f,a1=0.f,a2=0.f, b0=0.f,b1=1.f,b2=0.f, c0=0.f,c1=0.f,c2=1.f;
    float x=0.f, y=0.f, z=0.f;
    if (act) {
        a0=e0i[p*3+0]; a1=e0i[p*3+1]; a2=e0i[p*3+2];
        b0=e1i[p*3+0]; b1=e1i[p*3+1]; b2=e1i[p*3+2];
        c0=e2i[p*3+0]; c1=e2i[p*3+1]; c2=e2i[p*3+2];
        x =x0 [p*3+0]; y =x0 [p*3+1]; z =x0 [p*3+2];
    }

    for (int t0 = 0; t0 < N; t0 += TT) {
        #pragma unroll
        for (int k = 0; k < PPB; k++) {
            int gp = pbase + k;
            float vs=0.f, vp=0.f, vn=0.f;
            if (gp < B && t0 + lane < N) {
                size_t gidx = (size_t)gp * N + (size_t)t0 + lane;
                vs = spd[gidx]; vp = pan[gidx]; vn = nan_[gidx];
            }
            s_sp[lane][k]=vs; s_pa[lane][k]=vp; s_na[lane][k]=vn;
        }
        __syncthreads();

        if (act) {
            int nt = (N - t0 < TT) ? (N - t0) : TT;
            for (int tt = 0; tt < nt; tt++) {
                frame_step(s_pa[tt][lane], s_na[tt][lane],
                           a0,a1,a2,b0,b1,b2,c0,c1,c2);
                float sv = s_sp[tt][lane];
                x = fmaf(sv,a0,x); y = fmaf(sv,a1,y); z = fmaf(sv,a2,z);
                s_X[3*tt+0][lane]=x; s_X[3*tt+1][lane]=y; s_X[3*tt+2][lane]=z;
            }
            float inv = rsqrtf(fmaf(a0,a0, fmaf(a1,a1, a2*a2)));
            a0*=inv; a1*=inv; a2*=inv;
            float d = fmaf(b0,a0, fmaf(b1,a1, b2*a2));
            b0=fmaf(-d,a0,b0); b1=fmaf(-d,a1,b1); b2=fmaf(-d,a2,b2);
            inv = rsqrtf(fmaf(b0,b0, fmaf(b1,b1, b2*b2)));
            b0*=inv; b1*=inv; b2*=inv;
            c0=a1*b2-a2*b1; c1=a2*b0-a0*b2; c2=a0*b1-a1*b0;
        }
        __syncthreads();

        #pragma unroll
        for (int k = 0; k < PPB; k++) {
            int gp = pbase + k;
            if (gp < B) {
                size_t bidx = (size_t)gp*3*N + (size_t)t0*3;
                #pragma unroll
                for (int chn = 0; chn < 3; chn++)
                    if (t0*3 + chn*32 + lane < 3*N)
                        X[bidx + chn*32 + lane] = s_X[chn*32 + lane][k];
            }
        }
    }
}

__global__ void ts_kernel(float* __restrict__ ts, int N, const int* __restrict__ dtp)
{
    int i = blockIdx.x * blockDim.x + threadIdx.x;
    if (i >= N) return;
    float dtf = 1.0f;
    if (dtp != nullptr) {
        int v = dtp[0];
        if (v >= 1 && v <= 1000000) dtf = (float)v;
        else { float f = __int_as_float(v); if (f > 0.0f && f < 1.0e6f) dtf = f; }
    }
    ts[i] = (float)i * dtf;
}

// ---------------------------------------------------------------------------
extern "C" void kernel_launch(void* const* d_in, const int* in_sizes, int n_in,
                              void* d_out, int out_size)
{
    const float* x0   = (const float*)d_in[0];
    const float* e0   = (const float*)d_in[1];
    const float* e1   = (const float*)d_in[2];
    const float* e2   = (const float*)d_in[3];
    const float* spd  = (const float*)d_in[4];
    const float* pan  = (const float*)d_in[5];
    const float* nan_ = (const float*)d_in[6];

    const int B = in_sizes[0] / 3;
    const int N = (int)((long long)in_sizes[4] / B);

    float* out    = (float*)d_out;
    float* ts     = out;
    float* X      = out + N;
    float* states = X + (size_t)3 * B * N;
    float* sp_o   = states + (size_t)B * N;
    float* pa_o   = sp_o   + (size_t)B * N;
    float* na_o   = pa_o   + (size_t)B * N;

    const int* dtp = (n_in > 8) ? (const int*)d_in[8] : nullptr;

    const size_t smem_bytes = (size_t)SMEM_FLOATS * sizeof(float);  // ~13.7 KB
    const bool fast = (N == 1024);

    if (fast) {
        cudaFuncSetAttribute(fused_kernel,
                             cudaFuncAttributeMaxDynamicSharedMemorySize,
                             (int)smem_bytes);
        fused_kernel<<<B, THREADS, smem_bytes>>>(
            x0, e0, e1, e2, spd, pan, nan_,
            ts, X, states, sp_o, pa_o, na_o, dtp, B, N);
    } else {
        const size_t bn_bytes = (size_t)B * N * sizeof(float);
        explorer_kernel<<<(B + PPB - 1) / PPB, PPB>>>(x0, e0, e1, e2,
                                                      spd, pan, nan_, X, B, N);
        ts_kernel<<<(N + 255) / 256, 256>>>(ts, N, dtp);
        cudaMemsetAsync(states, 0, bn_bytes, 0);
        cudaMemcpyAsync(sp_o, d_in[4], bn_bytes, cudaMemcpyDeviceToDevice, 0);
        cudaMemcpyAsync(pa_o, d_in[5], bn_bytes, cudaMemcpyDeviceToDevice, 0);
        cudaMemcpyAsync(na_o, d_in[6], bn_bytes, cudaMemcpyDeviceToDevice, 0);
    }

    (void)out_size; (void)n_in;
}

// round 15
// speedup vs baseline: 1.3895x; 1.0043x over previous
#include <cuda_runtime.h>
#include <cstdint>

// ---------------------------------------------------------------------------
// ParticleExplorer — fused time-parallel kernel, L=8 chunks, 4 warps/particle,
// f32x2-packed arithmetic, streaming (ld.cs/st.cs) global accesses,
// 1 particle per 128-thread block, reg-capped for 12 blocks/SM (48 warps).
// Per step: E <- E * Rz(pa) * Ry(na);  x <- x + sp * E.col0
// N = 1024 = 128 chunks x 8 steps.
// Output: ts[N] | X[B][N][3] | states[B][N]=0 | speeds | pa | na
// ---------------------------------------------------------------------------

#define LCH 8
#define NWARP 4
#define THREADS (NWARP * 32)

#define SIN_PITCH 36
#define SIN_W (LCH * SIN_PITCH)                       // 288 floats per array
#define GLUE_OFF (NWARP * (3 * SIN_W))                // 3456
#define SMEM_FLOATS (GLUE_OFF + 48)                   // + glue (4 x 12)

typedef unsigned long long u64;

__device__ __forceinline__ u64 pk2(float lo, float hi) {
    u64 r; asm("mov.b64 %0,{%1,%2};" : "=l"(r) : "f"(lo), "f"(hi)); return r;
}
__device__ __forceinline__ void up2(u64 v, float& lo, float& hi) {
    asm("mov.b64 {%0,%1},%2;" : "=f"(lo), "=f"(hi) : "l"(v));
}
__device__ __forceinline__ u64 bc2(float s) { return pk2(s, s); }
__device__ __forceinline__ u64 fma2(u64 a, u64 b, u64 c) {
    u64 d; asm("fma.rn.f32x2 %0,%1,%2,%3;" : "=l"(d) : "l"(a), "l"(b), "l"(c)); return d;
}
__device__ __forceinline__ u64 mul2(u64 a, u64 b) {
    u64 d; asm("mul.rn.f32x2 %0,%1,%2;" : "=l"(d) : "l"(a), "l"(b)); return d;
}

// Affine element: columns e0,e1,e2 + displacement, components (0,1) packed.
struct Aff {
    u64 A, B, C, D;
    float a2, b2, c2, d2;
};

__device__ __forceinline__ Aff aff_identity() {
    Aff o;
    o.A = pk2(1.f, 0.f); o.a2 = 0.f;
    o.B = pk2(0.f, 1.f); o.b2 = 0.f;
    o.C = pk2(0.f, 0.f); o.c2 = 1.f;
    o.D = pk2(0.f, 0.f); o.d2 = 0.f;
    return o;
}

// compose: r earlier, q later (q's coeffs in r's start basis).
__device__ __forceinline__ Aff compose_p(const Aff& r, const Aff& q) {
    Aff o; float q0, q1, q2;
    up2(q.A, q0, q1); q2 = q.a2;
    o.A  = fma2(bc2(q0), r.A, fma2(bc2(q1), r.B, mul2(bc2(q2), r.C)));
    o.a2 = fmaf(q0, r.a2, fmaf(q1, r.b2, q2 * r.c2));
    up2(q.B, q0, q1); q2 = q.b2;
    o.B  = fma2(bc2(q0), r.A, fma2(bc2(q1), r.B, mul2(bc2(q2), r.C)));
    o.b2 = fmaf(q0, r.a2, fmaf(q1, r.b2, q2 * r.c2));
    up2(q.C, q0, q1); q2 = q.c2;
    o.C  = fma2(bc2(q0), r.A, fma2(bc2(q1), r.B, mul2(bc2(q2), r.C)));
    o.c2 = fmaf(q0, r.a2, fmaf(q1, r.b2, q2 * r.c2));
    up2(q.D, q0, q1); q2 = q.d2;
    o.D  = fma2(bc2(q0), r.A, fma2(bc2(q1), r.B, fma2(bc2(q2), r.C, r.D)));
    o.d2 = fmaf(q0, r.a2, fmaf(q1, r.b2, fmaf(q2, r.c2, r.d2)));
    return o;
}

__device__ __forceinline__ Aff shfl_up_aff(const Aff& v, int off) {
    Aff o;
    o.A  = __shfl_up_sync(0xffffffffu, v.A,  off);
    o.B  = __shfl_up_sync(0xffffffffu, v.B,  off);
    o.C  = __shfl_up_sync(0xffffffffu, v.C,  off);
    o.D  = __shfl_up_sync(0xffffffffu, v.D,  off);
    o.a2 = __shfl_up_sync(0xffffffffu, v.a2, off);
    o.b2 = __shfl_up_sync(0xffffffffu, v.b2, off);
    o.c2 = __shfl_up_sync(0xffffffffu, v.c2, off);
    o.d2 = __shfl_up_sync(0xffffffffu, v.d2, off);
    return o;
}

// Packed step: E <- E * Rz(pa) * Ry(na).
__device__ __forceinline__ void frame_step_p(float pa, float na,
    u64& A, u64& B, u64& C, float& a2, float& b2, float& c2)
{
    float s1, cc1, s2, cc2;
    __sincosf(pa, &s1, &cc1);
    __sincosf(na, &s2, &cc2);
    float p00 = cc1 * cc2, p10 = s1 * cc2;
    float p02 = cc1 * s2,  p12 = s1 * s2;

    u64 nA = fma2(bc2(p00), A, fma2(bc2(p10), B, mul2(bc2(-s2), C)));
    float na2 = fmaf(p00, a2, fmaf(p10, b2, -s2 * c2));
    u64 nB = fma2(bc2(cc1), B, mul2(bc2(-s1), A));
    float nb2 = fmaf(cc1, b2, -s1 * a2);
    u64 nC = fma2(bc2(p02), A, fma2(bc2(p12), B, mul2(bc2(cc2), C)));
    float nc2 = fmaf(p02, a2, fmaf(p12, b2, cc2 * c2));
    A = nA; B = nB; C = nC; a2 = na2; b2 = nb2; c2 = nc2;
}

// Scalar frame step (fallback kernel only).
__device__ __forceinline__ void frame_step(float pa, float na,
    float& a0, float& a1, float& a2,
    float& b0, float& b1, float& b2,
    float& c0, float& c1, float& c2)
{
    float s1, cc1, s2, cc2;
    __sincosf(pa, &s1, &cc1);
    __sincosf(na, &s2, &cc2);
    float p00 = cc1 * cc2, p10 = s1 * cc2;
    float p02 = cc1 * s2,  p12 = s1 * s2;

    float na0 = fmaf(p00, a0, fmaf(p10, b0, -s2 * c0));
    float na1 = fmaf(p00, a1, fmaf(p10, b1, -s2 * c1));
    float na2 = fmaf(p00, a2, fmaf(p10, b2, -s2 * c2));
    float nb0 = fmaf(cc1, b0, -s1 * a0);
    float nb1 = fmaf(cc1, b1, -s1 * a1);
    float nb2 = fmaf(cc1, b2, -s1 * a2);
    float nc0 = fmaf(p02, a0, fmaf(p12, b0, cc2 * c0));
    float nc1 = fmaf(p02, a1, fmaf(p12, b1, cc2 * c1));
    float nc2 = fmaf(p02, a2, fmaf(p12, b2, cc2 * c2));
    a0 = na0; a1 = na1; a2 = na2;
    b0 = nb0; b1 = nb1; b2 = nb2;
    c0 = nc0; c1 = nc1; c2 = nc2;
}

__global__ void __launch_bounds__(THREADS, 12)
fused_kernel(const float* __restrict__ x0, const float* __restrict__ e0i,
             const float* __restrict__ e1i, const float* __restrict__ e2i,
             const float* __restrict__ spd, const float* __restrict__ pan,
             const float* __restrict__ nanp,
             float* __restrict__ ts, float* __restrict__ X,
             float* __restrict__ states, float* __restrict__ spo,
             float* __restrict__ pao, float* __restrict__ nao,
             const int* __restrict__ dtp, int B, int N)
{
    extern __shared__ float sm[];

    const int tid  = threadIdx.x;
    const int lane = tid & 31;
    const int q    = tid >> 5;              // quarter of the timeline (warp id)
    const int p    = blockIdx.x;            // one particle per block
    const int gtid = blockIdx.x * THREADS + tid;

    if (gtid < N) {
        float dtf = 1.0f;
        if (dtp) {
            int vdt = dtp[0];
            if (vdt >= 1 && vdt <= 1000000) dtf = (float)vdt;
            else { float f = __int_as_float(vdt); if (f > 0.f && f < 1.0e6f) dtf = f; }
        }
        ts[gtid] = (float)gtid * dtf;
    }

    float* s_sp = sm + q * (3 * SIN_W);
    float* s_pa = s_sp + SIN_W;
    float* s_na = s_sp + 2 * SIN_W;
    float* glue = sm + GLUE_OFF;             // 4 totals x 12 floats

    const size_t pb = (size_t)p * N + (size_t)q * 256;
    const float4* g_sp = (const float4*)(spd  + pb);
    const float4* g_pa = (const float4*)(pan  + pb);
    const float4* g_na = (const float4*)(nanp + pb);
    float4* o_sp = (float4*)(spo    + pb);
    float4* o_pa = (float4*)(pao    + pb);
    float4* o_na = (float4*)(nao    + pb);
    float4* o_st = (float4*)(states + pb);
    const float4 zero4 = make_float4(0.f, 0.f, 0.f, 0.f);

    // ---- Stage: streaming loads -> smem [step i][chunk c], pitch 36;
    //      aux outputs written with streaming stores (read-once/write-once).
    #pragma unroll
    for (int j = 0; j < 2; j++) {
        int f = j * 32 + lane;
        float4 vs = __ldcs(&g_sp[f]);
        float4 vp = __ldcs(&g_pa[f]);
        float4 vn = __ldcs(&g_na[f]);
        __stcs(&o_sp[f], vs); __stcs(&o_pa[f], vp);
        __stcs(&o_na[f], vn); __stcs(&o_st[f], zero4);
        int c  = 16 * j + (lane >> 1);
        int i0 = (lane & 1) << 2;
        s_sp[(i0+0)*SIN_PITCH + c] = vs.x; s_sp[(i0+1)*SIN_PITCH + c] = vs.y;
        s_sp[(i0+2)*SIN_PITCH + c] = vs.z; s_sp[(i0+3)*SIN_PITCH + c] = vs.w;
        s_pa[(i0+0)*SIN_PITCH + c] = vp.x; s_pa[(i0+1)*SIN_PITCH + c] = vp.y;
        s_pa[(i0+2)*SIN_PITCH + c] = vp.z; s_pa[(i0+3)*SIN_PITCH + c] = vp.w;
        s_na[(i0+0)*SIN_PITCH + c] = vn.x; s_na[(i0+1)*SIN_PITCH + c] = vn.y;
        s_na[(i0+2)*SIN_PITCH + c] = vn.z; s_na[(i0+3)*SIN_PITCH + c] = vn.w;
    }
    __syncwarp();

    // ---- Pass 1: 8-step packed chunk transform; d_i overwrites inputs ----------
    u64 A = pk2(1.f, 0.f), Bv = pk2(0.f, 1.f), C = pk2(0.f, 0.f);
    float a2 = 0.f, b2 = 0.f, c2 = 1.f;
    u64 D = pk2(0.f, 0.f);
    float d2 = 0.f;
    #pragma unroll
    for (int i = 0; i < LCH; i++) {
        float pa = s_pa[i*SIN_PITCH + lane];
        float na = s_na[i*SIN_PITCH + lane];
        float sp = s_sp[i*SIN_PITCH + lane];
        frame_step_p(pa, na, A, Bv, C, a2, b2, c2);
        D  = fma2(bc2(sp), A, D);
        d2 = fmaf(sp, a2, d2);
        float dd0, dd1; up2(D, dd0, dd1);
        s_sp[i*SIN_PITCH + lane] = dd0;
        s_pa[i*SIN_PITCH + lane] = dd1;
        s_na[i*SIN_PITCH + lane] = d2;
    }

    Aff v; v.A = A; v.B = Bv; v.C = C; v.D = D;
    v.a2 = a2; v.b2 = b2; v.c2 = c2; v.d2 = d2;

    // ---- Intra-warp inclusive scan (packed affine composition) ----------------
    #pragma unroll
    for (int off = 1; off <= 16; off <<= 1) {
        Aff o = shfl_up_aff(v, off);
        if (lane >= off) v = compose_p(o, v);
    }

    // Publish each quarter's total (lane 31 inclusive) as 12 floats.
    if (lane == 31) {
        float t0, t1;
        up2(v.A, t0, t1); glue[q*12+0] = t0; glue[q*12+1] = t1; glue[q*12+2]  = v.a2;
        up2(v.B, t0, t1); glue[q*12+3] = t0; glue[q*12+4] = t1; glue[q*12+5]  = v.b2;
        up2(v.C, t0, t1); glue[q*12+6] = t0; glue[q*12+7] = t1; glue[q*12+8]  = v.c2;
        up2(v.D, t0, t1); glue[q*12+9] = t0; glue[q*12+10] = t1; glue[q*12+11] = v.d2;
    }
    __syncthreads();

    // Exclusive prefix within warp.
    Aff e = shfl_up_aff(v, 1);
    if (lane == 0) e = aff_identity();

    // Prepend earlier quarters' totals.
    if (q > 0) {
        Aff P;
        P.A = pk2(glue[0], glue[1]);  P.a2 = glue[2];
        P.B = pk2(glue[3], glue[4]);  P.b2 = glue[5];
        P.C = pk2(glue[6], glue[7]);  P.c2 = glue[8];
        P.D = pk2(glue[9], glue[10]); P.d2 = glue[11];
        for (int k = 1; k < q; k++) {
            Aff T;
            T.A = pk2(glue[k*12+0], glue[k*12+1]);  T.a2 = glue[k*12+2];
            T.B = pk2(glue[k*12+3], glue[k*12+4]);  T.b2 = glue[k*12+5];
            T.C = pk2(glue[k*12+6], glue[k*12+7]);  T.c2 = glue[k*12+8];
            T.D = pk2(glue[k*12+9], glue[k*12+10]); T.d2 = glue[k*12+11];
            P = compose_p(P, T);
        }
        e = compose_p(P, e);
    }

    // ---- Glue with particle initial frame/pos: one packed compose --------------
    Aff r0;
    r0.A = pk2(e0i[p*3+0], e0i[p*3+1]); r0.a2 = e0i[p*3+2];
    r0.B = pk2(e1i[p*3+0], e1i[p*3+1]); r0.b2 = e1i[p*3+2];
    r0.C = pk2(e2i[p*3+0], e2i[p*3+1]); r0.c2 = e2i[p*3+2];
    r0.D = pk2(x0 [p*3+0], x0 [p*3+1]); r0.d2 = x0 [p*3+2];
    Aff s = compose_p(r0, e);

    // Gram-Schmidt renorm (scalar; once per thread).
    float a0, a1, b0, b1, c0, c1, x, y, z;
    up2(s.A, a0, a1); a2 = s.a2;
    up2(s.B, b0, b1); b2 = s.b2;
    up2(s.D, x, y);   z  = s.d2;
    {
        float inv = rsqrtf(fmaf(a0,a0, fmaf(a1,a1, a2*a2)));
        a0*=inv; a1*=inv; a2*=inv;
        float dd = fmaf(b0,a0, fmaf(b1,a1, b2*a2));
        b0 = fmaf(-dd,a0,b0); b1 = fmaf(-dd,a1,b1); b2 = fmaf(-dd,a2,b2);
        inv = rsqrtf(fmaf(b0,b0, fmaf(b1,b1, b2*b2)));
        b0*=inv; b1*=inv; b2*=inv;
        c0 = a1*b2 - a2*b1;
        c1 = a2*b0 - a0*b2;
        c2 = a0*b1 - a1*b0;
    }
    A  = pk2(a0, a1);
    Bv = pk2(b0, b1);
    C  = pk2(c0, c1);
    u64 X01 = pk2(x, y);

    // ---- Pass 2: x_i = x_start + d_i . E_start (packed matvec), in place -------
    #pragma unroll
    for (int i = 0; i < LCH; i++) {
        float dd0 = s_sp[i*SIN_PITCH + lane];
        float dd1 = s_pa[i*SIN_PITCH + lane];
        float dd2 = s_na[i*SIN_PITCH + lane];
        u64 o01 = fma2(bc2(dd0), A, fma2(bc2(dd1), Bv, fma2(bc2(dd2), C, X01)));
        float oz = fmaf(dd0, a2, fmaf(dd1, b2, fmaf(dd2, c2, z)));
        float ox, oy; up2(o01, ox, oy);
        s_sp[i*SIN_PITCH + lane] = ox;
        s_pa[i*SIN_PITCH + lane] = oy;
        s_na[i*SIN_PITCH + lane] = oz;
    }
    __syncwarp();

    // ---- Flush X: 192 float4 per warp-quarter, x3-periodic addressing,
    //      streaming stores.
    float4* gX = (float4*)(X + (size_t)p * 3 * N + (size_t)q * 768);
    #pragma unroll
    for (int jc = 0; jc < 3; jc++) {
        const float* arr[4];
        int addr[4];
        #pragma unroll
        for (int k = 0; k < 4; k++) {
            int ek   = 128 * jc + 4 * lane + k;
            int own  = ek / 24;
            int rem  = ek - own * 24;
            int i    = rem / 3;
            int comp = rem - i * 3;
            arr[k]  = (comp == 0) ? s_sp : (comp == 1) ? s_pa : s_na;
            addr[k] = i * SIN_PITCH + own;
        }
        #pragma unroll
        for (int m = 0; m < 2; m++) {
            int j = jc + 3 * m;
            float4 r;
            r.x = arr[0][addr[0] + 16 * m];
            r.y = arr[1][addr[1] + 16 * m];
            r.z = arr[2][addr[2] + 16 * m];
            r.w = arr[3][addr[3] + 16 * m];
            __stcs(&gX[j * 32 + lane], r);
        }
    }
}

// ---------------------------------------------------------------------------
// Fallback (proven round-2 path) for unexpected shapes.
// ---------------------------------------------------------------------------
#define PPB 32
#define TT  32
#define SPITCH 33

__global__ void __launch_bounds__(PPB)
explorer_kernel(const float* __restrict__ x0, const float* __restrict__ e0i,
                const float* __restrict__ e1i, const float* __restrict__ e2i,
                const float* __restrict__ spd, const float* __restrict__ pan,
                const float* __restrict__ nan_, float* __restrict__ X,
                int B, int N)
{
    __shared__ float s_sp[TT][SPITCH];
    __shared__ float s_pa[TT][SPITCH];
    __shared__ float s_na[TT][SPITCH];
    __shared__ float s_X[3 * TT][SPITCH];

    const int lane  = threadIdx.x;
    const int pbase = blockIdx.x * PPB;
    const int p     = pbase + lane;
    const bool act  = (p < B);

    float a0=1.f,a1=0.f,a2=0.f, b0=0.f,b1=1.f,b2=0.f, c0=0.f,c1=0.f,c2=1.f;
    float x=0.f, y=0.f, z=0.f;
    if (act) {
        a0=e0i[p*3+0]; a1=e0i[p*3+1]; a2=e0i[p*3+2];
        b0=e1i[p*3+0]; b1=e1i[p*3+1]; b2=e1i[p*3+2];
        c0=e2i[p*3+0]; c1=e2i[p*3+1]; c2=e2i[p*3+2];
        x =x0 [p*3+0]; y =x0 [p*3+1]; z =x0 [p*3+2];
    }

    for (int t0 = 0; t0 < N; t0 += TT) {
        #pragma unroll
        for (int k = 0; k < PPB; k++) {
            int gp = pbase + k;
            float vs=0.f, vp=0.f, vn=0.f;
            if (gp < B && t0 + lane < N) {
                size_t gidx = (size_t)gp * N + (size_t)t0 + lane;
                vs = spd[gidx]; vp = pan[gidx]; vn = nan_[gidx];
            }
            s_sp[lane][k]=vs; s_pa[lane][k]=vp; s_na[lane][k]=vn;
        }
        __syncthreads();

        if (act) {
            int nt = (N - t0 < TT) ? (N - t0) : TT;
            for (int tt = 0; tt < nt; tt++) {
                frame_step(s_pa[tt][lane], s_na[tt][lane],
                           a0,a1,a2,b0,b1,b2,c0,c1,c2);
                float sv = s_sp[tt][lane];
                x = fmaf(sv,a0,x); y = fmaf(sv,a1,y); z = fmaf(sv,a2,z);
                s_X[3*tt+0][lane]=x; s_X[3*tt+1][lane]=y; s_X[3*tt+2][lane]=z;
            }
            float inv = rsqrtf(fmaf(a0,a0, fmaf(a1,a1, a2*a2)));
            a0*=inv; a1*=inv; a2*=inv;
            float d = fmaf(b0,a0, fmaf(b1,a1, b2*a2));
            b0=fmaf(-d,a0,b0); b1=fmaf(-d,a1,b1); b2=fmaf(-d,a2,b2);
            inv = rsqrtf(fmaf(b0,b0, fmaf(b1,b1, b2*b2)));
            b0*=inv; b1*=inv; b2*=inv;
            c0=a1*b2-a2*b1; c1=a2*b0-a0*b2; c2=a0*b1-a1*b0;
        }
        __syncthreads();

        #pragma unroll
        for (int k = 0; k < PPB; k++) {
            int gp = pbase + k;
            if (gp < B) {
                size_t bidx = (size_t)gp*3*N + (size_t)t0*3;
                #pragma unroll
                for (int chn = 0; chn < 3; chn++)
                    if (t0*3 + chn*32 + lane < 3*N)
                        X[bidx + chn*32 + lane] = s_X[chn*32 + lane][k];
            }
        }
    }
}

__global__ void ts_kernel(float* __restrict__ ts, int N, const int* __restrict__ dtp)
{
    int i = blockIdx.x * blockDim.x + threadIdx.x;
    if (i >= N) return;
    float dtf = 1.0f;
    if (dtp != nullptr) {
        int v = dtp[0];
        if (v >= 1 && v <= 1000000) dtf = (float)v;
        else { float f = __int_as_float(v); if (f > 0.0f && f < 1.0e6f) dtf = f; }
    }
    ts[i] = (float)i * dtf;
}

// ---------------------------------------------------------------------------
extern "C" void kernel_launch(void* const* d_in, const int* in_sizes, int n_in,
                              void* d_out, int out_size)
{
    const float* x0   = (const float*)d_in[0];
    const float* e0   = (const float*)d_in[1];
    const float* e1   = (const float*)d_in[2];
    const float* e2   = (const float*)d_in[3];
    const float* spd  = (const float*)d_in[4];
    const float* pan  = (const float*)d_in[5];
    const float* nan_ = (const float*)d_in[6];

    const int B = in_sizes[0] / 3;
    const int N = (int)((long long)in_sizes[4] / B);

    float* out    = (float*)d_out;
    float* ts     = out;
    float* X      = out + N;
    float* states = X + (size_t)3 * B * N;
    float* sp_o   = states + (size_t)B * N;
    float* pa_o   = sp_o   + (size_t)B * N;
    float* na_o   = pa_o   + (size_t)B * N;

    const int* dtp = (n_in > 8) ? (const int*)d_in[8] : nullptr;

    const size_t smem_bytes = (size_t)SMEM_FLOATS * sizeof(float);  // ~13.7 KB
    const bool fast = (N == 1024);

    if (fast) {
        cudaFuncSetAttribute(fused_kernel,
                             cudaFuncAttributeMaxDynamicSharedMemorySize,
                             (int)smem_bytes);
        fused_kernel<<<B, THREADS, smem_bytes>>>(
            x0, e0, e1, e2, spd, pan, nan_,
            ts, X, states, sp_o, pa_o, na_o, dtp, B, N);
    } else {
        const size_t bn_bytes = (size_t)B * N * sizeof(float);
        explorer_kernel<<<(B + PPB - 1) / PPB, PPB>>>(x0, e0, e1, e2,
                                                      spd, pan, nan_, X, B, N);
        ts_kernel<<<(N + 255) / 256, 256>>>(ts, N, dtp);
        cudaMemsetAsync(states, 0, bn_bytes, 0);
        cudaMemcpyAsync(sp_o, d_in[4], bn_bytes, cudaMemcpyDeviceToDevice, 0);
        cudaMemcpyAsync(pa_o, d_in[5], bn_bytes, cudaMemcpyDeviceToDevice, 0);
        cudaMemcpyAsync(na_o, d_in[6], bn_bytes, cudaMemcpyDeviceToDevice, 0);
    }

    (void)out_size; (void)n_in;
}